// round 5
// baseline (speedup 1.0000x reference)
#include <cuda_runtime.h>
#include <math.h>

namespace {

constexpr int B_ = 2;
constexpr int S_ = 2048;
constexpr int H_ = 16;
constexpr int D_ = 64;
constexpr int E_ = 1024;
constexpr int MROWS = B_ * S_;   // 4096

// Scratch (device globals: allocation-free per harness rules)
__device__ float g_q[(size_t)B_ * H_ * S_ * D_];   // [b,h,s,d]
__device__ float g_k[(size_t)B_ * H_ * S_ * D_];
__device__ float g_v[(size_t)B_ * H_ * S_ * D_];
__device__ float g_ao[(size_t)MROWS * E_];          // [b,s,e] attention output

// Input pointers resolved ON DEVICE by the classifier kernel.
__device__ const float* g_in_x;
__device__ const float* g_in_qkv_w;
__device__ const float* g_in_qkv_b;
__device__ const float* g_in_proj_w;
__device__ const float* g_in_proj_b;

struct InArgs {
    const float* p[8];
    long long    sz[8];
    int          n;
};

// ---------------------------------------------------------------------------
// Classifier: identify inputs by size rank + data statistics. No assumptions
// about argument order, mask presence, or whether sizes are bytes/elements.
//   - two smallest sizes  -> proj_b (smallest), qkv_b (2nd smallest)
//   - x = unique remaining tensor with mean(x^2) ~ 1 over first 2048 floats
//   - of the remaining non-x tensors, the two SMALLEST are proj_w < qkv_w
//     (a mask input, if present, is the largest and is excluded)
// ---------------------------------------------------------------------------
__global__ __launch_bounds__(256)
void classify_kernel(InArgs a)
{
    __shared__ float red[256];
    __shared__ float msq[8];
    const int tid = threadIdx.x;

    for (int c = 0; c < a.n; c++) {
        float s = 0.f;
        #pragma unroll
        for (int i = tid; i < 2048; i += 256) {
            const float v = a.p[c][i];
            s += v * v;
        }
        red[tid] = s;
        __syncthreads();
        for (int st = 128; st; st >>= 1) {
            if (tid < st) red[tid] += red[tid + st];
            __syncthreads();
        }
        if (tid == 0) msq[c] = red[0] * (1.f / 2048.f);
        __syncthreads();
    }

    if (tid == 0) {
        // sort indices by size ascending
        int ord[8];
        for (int i = 0; i < a.n; i++) ord[i] = i;
        for (int i = 1; i < a.n; i++) {
            const int o = ord[i];
            const long long s = a.sz[o];
            int j = i - 1;
            while (j >= 0 && a.sz[ord[j]] > s) { ord[j + 1] = ord[j]; j--; }
            ord[j + 1] = o;
        }
        g_in_proj_b = a.p[ord[0]];
        g_in_qkv_b  = a.p[ord[1]];

        // x: mean-square in [0.3, 3] (N(0,1) data). Others are ~1e-3 or ~0.
        int xi = -1;
        for (int r = 2; r < a.n; r++) {
            const float m = msq[ord[r]];
            if (m > 0.3f && m < 3.f) { xi = ord[r]; break; }
        }
        // weights: two smallest remaining sizes, excluding x
        int w0 = -1, w1 = -1;
        for (int r = 2; r < a.n; r++) {
            if (ord[r] == xi) continue;
            if (w0 < 0) { w0 = ord[r]; continue; }
            if (w1 < 0) { w1 = ord[r]; break; }
        }
        g_in_proj_w = a.p[w0];   // smaller weight  (E*E)
        g_in_qkv_w  = a.p[w1];   // larger weight   (3E*E)
        if (xi < 0) {
            // statistical window failed: fall back to expected ascending rank
            // [proj_b, qkv_b, proj_w, qkv_w, x, (mask)]
            xi = (a.n >= 5) ? ord[4] : ord[a.n - 1];
        }
        g_in_x = a.p[xi];
    }
}

// ---------------------------------------------------------------------------
// SGEMM: C[m,n] = sum_k A[m,k] * W[n,k] + bias[n]   (A @ W^T + b)
// BM=BN=128, BK=16, 8x8 per thread, 256 threads.
// QKV=true : A=g_in_x, W=g_in_qkv_w, bias=g_in_qkv_b, scatter into g_q/g_k/g_v
// QKV=false: A=g_ao,   W=g_in_proj_w, bias=g_in_proj_b, write C
// ---------------------------------------------------------------------------
template <int N, int K, bool QKV>
__global__ __launch_bounds__(256)
void sgemm_kernel(float* __restrict__ C)
{
    const float* A    = QKV ? g_in_x     : g_ao;
    const float* W    = QKV ? g_in_qkv_w : g_in_proj_w;
    const float* bias = QKV ? g_in_qkv_b : g_in_proj_b;

    constexpr int BM = 128, BN = 128, BK = 16;
    __shared__ float As[BK][BM + 4];
    __shared__ float Bs[BK][BN + 4];

    const int tid  = threadIdx.x;
    const int tRow = tid >> 4;          // 0..15
    const int tCol = tid & 15;          // 0..15

    const int rowA = blockIdx.y * BM;
    const int colB = blockIdx.x * BN;
    const float* Ab = A + (size_t)rowA * K;
    const float* Wb = W + (size_t)colB * K;

    float acc[8][8] = {};

    for (int kt = 0; kt < K; kt += BK) {
        #pragma unroll
        for (int i = tid; i < BM * BK; i += 256) {
            const int r = i >> 4;
            const int c = i & 15;
            As[c][r] = Ab[(size_t)r * K + kt + c];
            Bs[c][r] = Wb[(size_t)r * K + kt + c];
        }
        __syncthreads();

        #pragma unroll
        for (int k = 0; k < BK; k++) {
            float ra[8], rb[8];
            #pragma unroll
            for (int i = 0; i < 8; i++) ra[i] = As[k][tRow * 8 + i];
            #pragma unroll
            for (int j = 0; j < 8; j++) rb[j] = Bs[k][tCol * 8 + j];
            #pragma unroll
            for (int i = 0; i < 8; i++)
                #pragma unroll
                for (int j = 0; j < 8; j++)
                    acc[i][j] = fmaf(ra[i], rb[j], acc[i][j]);
        }
        __syncthreads();
    }

    if (QKV) {
        const int which = colB >> 10;  // 0:q 1:k 2:v (1024 channels each)
        float* dst = (which == 0) ? g_q : (which == 1) ? g_k : g_v;
        #pragma unroll
        for (int i = 0; i < 8; i++) {
            const int m = rowA + tRow * 8 + i;
            const int b = m >> 11, s = m & (S_ - 1);
            #pragma unroll
            for (int j = 0; j < 8; j++) {
                const int n = colB + tCol * 8 + j;
                const int c = n & (E_ - 1);
                const int h = c >> 6, d = c & (D_ - 1);
                dst[(((size_t)(b * H_ + h)) * S_ + s) * D_ + d] = acc[i][j] + bias[n];
            }
        }
    } else {
        #pragma unroll
        for (int i = 0; i < 8; i++) {
            const int m = rowA + tRow * 8 + i;
            #pragma unroll
            for (int j = 0; j < 8; j++) {
                const int n = colB + tCol * 8 + j;
                C[(size_t)m * N + n] = acc[i][j] + bias[n];
            }
        }
    }
}

// ---------------------------------------------------------------------------
// Causal flash attention, fp32. Br=64, Bc=32, D=64.
// 256 threads = 16(ty) x 16(tx). s[4][2] per thread, o[4][4] per thread.
// ---------------------------------------------------------------------------
__global__ __launch_bounds__(256)
void flash_attn_kernel()
{
    const int qi = blockIdx.x;   // q tile, 0..31
    const int bh = blockIdx.y;   // 0..31 = b*H + h
    const float* Qg = g_q + (size_t)bh * S_ * D_;
    const float* Kg = g_k + (size_t)bh * S_ * D_;
    const float* Vg = g_v + (size_t)bh * S_ * D_;

    __shared__ float Qs[64][65];   // [q-row][d], pre-scaled
    __shared__ float Ks[32][65];   // [kv-row][d]
    __shared__ float Vt[64][33];   // [d][kv-row]  (transposed)
    __shared__ float Ps[64][33];   // [q-row][kv-row]

    const int tid = threadIdx.x;
    const int ty = tid >> 4;
    const int tx = tid & 15;
    const float scale = 0.125f;      // D^-0.5

    for (int i = tid; i < 64 * 64; i += 256) {
        const int r = i >> 6, c = i & 63;
        Qs[r][c] = Qg[(size_t)(qi * 64 + r) * D_ + c] * scale;
    }

    float m_i[4], l_i[4], o[4][4];
    #pragma unroll
    for (int i = 0; i < 4; i++) {
        m_i[i] = -1e30f; l_i[i] = 0.f;
        #pragma unroll
        for (int j = 0; j < 4; j++) o[i][j] = 0.f;
    }

    const int ntiles = 2 * qi + 2;
    for (int jt = 0; jt < ntiles; jt++) {
        const int kv0 = jt * 32;
        __syncthreads();

        for (int i = tid; i < 32 * 64; i += 256) {
            const int r = i >> 6, c = i & 63;
            Ks[r][c] = Kg[(size_t)(kv0 + r) * D_ + c];
            Vt[c][r] = Vg[(size_t)(kv0 + r) * D_ + c];
        }
        __syncthreads();

        float s[4][2] = {};
        #pragma unroll 4
        for (int d = 0; d < 64; d++) {
            float qa[4], ka[2];
            #pragma unroll
            for (int i = 0; i < 4; i++) qa[i] = Qs[ty * 4 + i][d];
            #pragma unroll
            for (int jj = 0; jj < 2; jj++) ka[jj] = Ks[tx * 2 + jj][d];
            #pragma unroll
            for (int i = 0; i < 4; i++)
                #pragma unroll
                for (int jj = 0; jj < 2; jj++)
                    s[i][jj] = fmaf(qa[i], ka[jj], s[i][jj]);
        }

        if (jt >= 2 * qi) {
            #pragma unroll
            for (int i = 0; i < 4; i++) {
                const int qrow = qi * 64 + ty * 4 + i;
                #pragma unroll
                for (int jj = 0; jj < 2; jj++)
                    if (kv0 + tx * 2 + jj > qrow) s[i][jj] = -1e30f;
            }
        }

        float p[4][2];
        #pragma unroll
        for (int i = 0; i < 4; i++) {
            float mt = fmaxf(s[i][0], s[i][1]);
            #pragma unroll
            for (int off = 8; off; off >>= 1)
                mt = fmaxf(mt, __shfl_xor_sync(0xffffffffu, mt, off, 16));
            const float m_new = fmaxf(m_i[i], mt);
            const float alpha = __expf(m_i[i] - m_new);
            m_i[i] = m_new;
            float sum = 0.f;
            #pragma unroll
            for (int jj = 0; jj < 2; jj++) {
                p[i][jj] = __expf(s[i][jj] - m_new);
                sum += p[i][jj];
            }
            #pragma unroll
            for (int off = 8; off; off >>= 1)
                sum += __shfl_xor_sync(0xffffffffu, sum, off, 16);
            l_i[i] = l_i[i] * alpha + sum;
            #pragma unroll
            for (int j = 0; j < 4; j++) o[i][j] *= alpha;
        }

        #pragma unroll
        for (int i = 0; i < 4; i++)
            #pragma unroll
            for (int jj = 0; jj < 2; jj++)
                Ps[ty * 4 + i][tx * 2 + jj] = p[i][jj];
        __syncthreads();

        #pragma unroll 4
        for (int c = 0; c < 32; c++) {
            float pa[4], va[4];
            #pragma unroll
            for (int i = 0; i < 4; i++) pa[i] = Ps[ty * 4 + i][c];
            #pragma unroll
            for (int j = 0; j < 4; j++) va[j] = Vt[tx * 4 + j][c];
            #pragma unroll
            for (int i = 0; i < 4; i++)
                #pragma unroll
                for (int j = 0; j < 4; j++)
                    o[i][j] = fmaf(pa[i], va[j], o[i][j]);
        }
    }

    const int b = bh >> 4, h = bh & 15;
    #pragma unroll
    for (int i = 0; i < 4; i++) {
        const float inv = 1.f / l_i[i];
        const int qr = qi * 64 + ty * 4 + i;
        float* dst = g_ao + ((size_t)(b * S_ + qr)) * E_ + h * 64 + tx * 4;
        #pragma unroll
        for (int j = 0; j < 4; j++) dst[j] = o[i][j] * inv;
    }
}

}  // namespace

extern "C" void kernel_launch(void* const* d_in, const int* in_sizes, int n_in,
                              void* d_out, int out_size)
{
    (void)out_size;
    InArgs a;
    a.n = (n_in < 8) ? n_in : 8;
    for (int i = 0; i < 8; i++) {
        a.p[i]  = (i < a.n) ? (const float*)d_in[i] : nullptr;
        a.sz[i] = (i < a.n) ? (long long)in_sizes[i] : 0;
    }

    // 0) Identify inputs on-device from sizes + data statistics
    classify_kernel<<<1, 256>>>(a);

    // 1) QKV GEMM with fused bias + scatter into [b,h,s,d]
    {
        dim3 grid(3 * E_ / 128, MROWS / 128);
        sgemm_kernel<3 * E_, E_, true><<<grid, 256>>>(nullptr);
    }
    // 2) Causal flash attention
    {
        dim3 grid(S_ / 64, B_ * H_);
        flash_attn_kernel<<<grid, 256>>>();
    }
    // 3) Output projection
    {
        dim3 grid(E_ / 128, MROWS / 128);
        sgemm_kernel<E_, E_, false><<<grid, 256>>>((float*)d_out);
    }
}

// round 6
// speedup vs baseline: 1.3342x; 1.3342x over previous
#include <cuda_runtime.h>
#include <math.h>
#include <stdint.h>

namespace {

constexpr int B_ = 2;
constexpr int S_ = 2048;
constexpr int H_ = 16;
constexpr int D_ = 64;
constexpr int E_ = 1024;
constexpr int MROWS = B_ * S_;   // 4096

// Scratch (device globals: allocation-free per harness rules)
__device__ float g_q[(size_t)B_ * H_ * S_ * D_];   // [b,h,s,d]
__device__ float g_k[(size_t)B_ * H_ * S_ * D_];
__device__ float g_v[(size_t)B_ * H_ * S_ * D_];
__device__ float g_ao[(size_t)MROWS * E_];          // [b,s,e] attention output

// Input pointers resolved ON DEVICE by the classifier kernel.
__device__ const float* g_in_x;
__device__ const float* g_in_qkv_w;
__device__ const float* g_in_qkv_b;
__device__ const float* g_in_proj_w;
__device__ const float* g_in_proj_b;

struct InArgs {
    const float* p[8];
    long long    sz[8];
    int          n;
};

// ---------------------------------------------------------------------------
// Classifier (UNCHANGED — this fixed the binding): identify inputs by size
// rank + data statistics, assumption-free about order/units/mask presence.
// ---------------------------------------------------------------------------
__global__ __launch_bounds__(256)
void classify_kernel(InArgs a)
{
    __shared__ float red[256];
    __shared__ float msq[8];
    const int tid = threadIdx.x;

    for (int c = 0; c < a.n; c++) {
        float s = 0.f;
        #pragma unroll
        for (int i = tid; i < 2048; i += 256) {
            const float v = a.p[c][i];
            s += v * v;
        }
        red[tid] = s;
        __syncthreads();
        for (int st = 128; st; st >>= 1) {
            if (tid < st) red[tid] += red[tid + st];
            __syncthreads();
        }
        if (tid == 0) msq[c] = red[0] * (1.f / 2048.f);
        __syncthreads();
    }

    if (tid == 0) {
        int ord[8];
        for (int i = 0; i < a.n; i++) ord[i] = i;
        for (int i = 1; i < a.n; i++) {
            const int o = ord[i];
            const long long s = a.sz[o];
            int j = i - 1;
            while (j >= 0 && a.sz[ord[j]] > s) { ord[j + 1] = ord[j]; j--; }
            ord[j + 1] = o;
        }
        g_in_proj_b = a.p[ord[0]];
        g_in_qkv_b  = a.p[ord[1]];

        int xi = -1;
        for (int r = 2; r < a.n; r++) {
            const float m = msq[ord[r]];
            if (m > 0.3f && m < 3.f) { xi = ord[r]; break; }
        }
        int w0 = -1, w1 = -1;
        for (int r = 2; r < a.n; r++) {
            if (ord[r] == xi) continue;
            if (w0 < 0) { w0 = ord[r]; continue; }
            if (w1 < 0) { w1 = ord[r]; break; }
        }
        g_in_proj_w = a.p[w0];
        g_in_qkv_w  = a.p[w1];
        if (xi < 0) xi = (a.n >= 5) ? ord[4] : ord[a.n - 1];
        g_in_x = a.p[xi];
    }
}

// ---------------------------------------------------------------------------
// tf32 tensor-core GEMM: C[m,n] = sum_k A[m,k]*W[n,k] + bias[n]  (A @ W^T + b)
// Block 128x128x32. 256 threads = 8 warps (2 m x 4 n), warp tile 64x32.
// mma.sync m16n8k8 tf32, fp32 accumulate. Inputs cvt.rna.tf32 at smem store.
// SMEM layout [k][m] with pad 133 -> conflict-free transposed stores.
// QKV=true : A=g_in_x, W=g_in_qkv_w, b=g_in_qkv_b, scatter into g_q/g_k/g_v
// QKV=false: A=g_ao,   W=g_in_proj_w, b=g_in_proj_b, write C row-major
// ---------------------------------------------------------------------------
__device__ __forceinline__ uint32_t f2tf32(float f) {
    uint32_t u;
    asm("cvt.rna.tf32.f32 %0, %1;" : "=r"(u) : "f"(f));
    return u;
}

template <int N, int K, bool QKV>
__global__ __launch_bounds__(256)
void tf32_gemm_kernel(float* __restrict__ C)
{
    const float* A    = QKV ? g_in_x     : g_ao;
    const float* W    = QKV ? g_in_qkv_w : g_in_proj_w;
    const float* bias = QKV ? g_in_qkv_b : g_in_proj_b;

    constexpr int BM = 128, BN = 128, BK = 32, PAD = 133;
    __shared__ uint32_t As[BK * PAD];   // [k][m], tf32 bits
    __shared__ uint32_t Bs[BK * PAD];   // [k][n], tf32 bits

    const int tid  = threadIdx.x;
    const int warp = tid >> 5;
    const int lane = tid & 31;
    const int wm = (warp & 1) * 64;     // warp m offset in block
    const int wn = (warp >> 1) * 32;    // warp n offset in block

    const int rowA = blockIdx.y * BM;
    const int colB = blockIdx.x * BN;
    const float* Ab = A + (size_t)rowA * K;
    const float* Wb = W + (size_t)colB * K;

    const int lr  = tid >> 3;           // 0..31: row within 32-row group
    const int lc4 = (tid & 7) << 2;     // 0..28: k column (float4 granularity)

    float acc[4][4][4] = {};            // [m-tile][n-tile][c-reg]

    const int qr = lane >> 2;           // frag group row 0..7
    const int qk = lane & 3;            // frag k lane  0..3

    for (int kt = 0; kt < K; kt += BK) {
        // Load 128x32 of A and W, cvt to tf32, store transposed [k][m]
        #pragma unroll
        for (int it = 0; it < 4; it++) {
            const int r = lr + it * 32;
            float4 av = *reinterpret_cast<const float4*>(Ab + (size_t)r * K + kt + lc4);
            float4 bv = *reinterpret_cast<const float4*>(Wb + (size_t)r * K + kt + lc4);
            As[(lc4 + 0) * PAD + r] = f2tf32(av.x);
            As[(lc4 + 1) * PAD + r] = f2tf32(av.y);
            As[(lc4 + 2) * PAD + r] = f2tf32(av.z);
            As[(lc4 + 3) * PAD + r] = f2tf32(av.w);
            Bs[(lc4 + 0) * PAD + r] = f2tf32(bv.x);
            Bs[(lc4 + 1) * PAD + r] = f2tf32(bv.y);
            Bs[(lc4 + 2) * PAD + r] = f2tf32(bv.z);
            Bs[(lc4 + 3) * PAD + r] = f2tf32(bv.w);
        }
        __syncthreads();

        #pragma unroll
        for (int ks = 0; ks < 4; ks++) {
            const int k0 = ks * 8;
            uint32_t af[4][4], bf[4][2];
            #pragma unroll
            for (int mt = 0; mt < 4; mt++) {
                const int m0 = wm + mt * 16;
                af[mt][0] = As[(k0 + qk    ) * PAD + m0 + qr    ];
                af[mt][1] = As[(k0 + qk    ) * PAD + m0 + qr + 8];
                af[mt][2] = As[(k0 + qk + 4) * PAD + m0 + qr    ];
                af[mt][3] = As[(k0 + qk + 4) * PAD + m0 + qr + 8];
            }
            #pragma unroll
            for (int nt = 0; nt < 4; nt++) {
                const int n0 = wn + nt * 8;
                bf[nt][0] = Bs[(k0 + qk    ) * PAD + n0 + qr];
                bf[nt][1] = Bs[(k0 + qk + 4) * PAD + n0 + qr];
            }
            #pragma unroll
            for (int mt = 0; mt < 4; mt++)
                #pragma unroll
                for (int nt = 0; nt < 4; nt++) {
                    float* c = acc[mt][nt];
                    asm volatile(
                        "mma.sync.aligned.m16n8k8.row.col.f32.tf32.tf32.f32 "
                        "{%0,%1,%2,%3}, {%4,%5,%6,%7}, {%8,%9}, {%0,%1,%2,%3};"
                        : "+f"(c[0]), "+f"(c[1]), "+f"(c[2]), "+f"(c[3])
                        : "r"(af[mt][0]), "r"(af[mt][1]), "r"(af[mt][2]), "r"(af[mt][3]),
                          "r"(bf[nt][0]), "r"(bf[nt][1]));
                }
        }
        __syncthreads();
    }

    // Epilogue. c-frag mapping: reg0:(qr, 2qk) reg1:(qr, 2qk+1) reg2:(qr+8, 2qk) reg3:(qr+8, 2qk+1)
    #pragma unroll
    for (int mt = 0; mt < 4; mt++) {
        #pragma unroll
        for (int nt = 0; nt < 4; nt++) {
            #pragma unroll
            for (int rg = 0; rg < 4; rg++) {
                const int m = rowA + wm + mt * 16 + qr + ((rg >> 1) << 3);
                const int n = colB + wn + nt * 8 + (qk << 1) + (rg & 1);
                const float v = acc[mt][nt][rg] + bias[n];
                if (QKV) {
                    const int which = n >> 10;   // 0:q 1:k 2:v
                    float* dst = (which == 0) ? g_q : (which == 1) ? g_k : g_v;
                    const int b = m >> 11, s = m & (S_ - 1);
                    const int c = n & (E_ - 1);
                    const int h = c >> 6, d = c & (D_ - 1);
                    dst[(((size_t)(b * H_ + h)) * S_ + s) * D_ + d] = v;
                } else {
                    C[(size_t)m * N + n] = v;
                }
            }
        }
    }
}

// ---------------------------------------------------------------------------
// Causal flash attention, fp32 (UNCHANGED from passing round).
// Br=64, Bc=32, D=64. 256 threads = 16(ty) x 16(tx).
// ---------------------------------------------------------------------------
__global__ __launch_bounds__(256)
void flash_attn_kernel()
{
    const int qi = blockIdx.x;
    const int bh = blockIdx.y;
    const float* Qg = g_q + (size_t)bh * S_ * D_;
    const float* Kg = g_k + (size_t)bh * S_ * D_;
    const float* Vg = g_v + (size_t)bh * S_ * D_;

    __shared__ float Qs[64][65];
    __shared__ float Ks[32][65];
    __shared__ float Vt[64][33];
    __shared__ float Ps[64][33];

    const int tid = threadIdx.x;
    const int ty = tid >> 4;
    const int tx = tid & 15;
    const float scale = 0.125f;

    for (int i = tid; i < 64 * 64; i += 256) {
        const int r = i >> 6, c = i & 63;
        Qs[r][c] = Qg[(size_t)(qi * 64 + r) * D_ + c] * scale;
    }

    float m_i[4], l_i[4], o[4][4];
    #pragma unroll
    for (int i = 0; i < 4; i++) {
        m_i[i] = -1e30f; l_i[i] = 0.f;
        #pragma unroll
        for (int j = 0; j < 4; j++) o[i][j] = 0.f;
    }

    const int ntiles = 2 * qi + 2;
    for (int jt = 0; jt < ntiles; jt++) {
        const int kv0 = jt * 32;
        __syncthreads();

        for (int i = tid; i < 32 * 64; i += 256) {
            const int r = i >> 6, c = i & 63;
            Ks[r][c] = Kg[(size_t)(kv0 + r) * D_ + c];
            Vt[c][r] = Vg[(size_t)(kv0 + r) * D_ + c];
        }
        __syncthreads();

        float s[4][2] = {};
        #pragma unroll 4
        for (int d = 0; d < 64; d++) {
            float qa[4], ka[2];
            #pragma unroll
            for (int i = 0; i < 4; i++) qa[i] = Qs[ty * 4 + i][d];
            #pragma unroll
            for (int jj = 0; jj < 2; jj++) ka[jj] = Ks[tx * 2 + jj][d];
            #pragma unroll
            for (int i = 0; i < 4; i++)
                #pragma unroll
                for (int jj = 0; jj < 2; jj++)
                    s[i][jj] = fmaf(qa[i], ka[jj], s[i][jj]);
        }

        if (jt >= 2 * qi) {
            #pragma unroll
            for (int i = 0; i < 4; i++) {
                const int qrow = qi * 64 + ty * 4 + i;
                #pragma unroll
                for (int jj = 0; jj < 2; jj++)
                    if (kv0 + tx * 2 + jj > qrow) s[i][jj] = -1e30f;
            }
        }

        float p[4][2];
        #pragma unroll
        for (int i = 0; i < 4; i++) {
            float mt = fmaxf(s[i][0], s[i][1]);
            #pragma unroll
            for (int off = 8; off; off >>= 1)
                mt = fmaxf(mt, __shfl_xor_sync(0xffffffffu, mt, off, 16));
            const float m_new = fmaxf(m_i[i], mt);
            const float alpha = __expf(m_i[i] - m_new);
            m_i[i] = m_new;
            float sum = 0.f;
            #pragma unroll
            for (int jj = 0; jj < 2; jj++) {
                p[i][jj] = __expf(s[i][jj] - m_new);
                sum += p[i][jj];
            }
            #pragma unroll
            for (int off = 8; off; off >>= 1)
                sum += __shfl_xor_sync(0xffffffffu, sum, off, 16);
            l_i[i] = l_i[i] * alpha + sum;
            #pragma unroll
            for (int j = 0; j < 4; j++) o[i][j] *= alpha;
        }

        #pragma unroll
        for (int i = 0; i < 4; i++)
            #pragma unroll
            for (int jj = 0; jj < 2; jj++)
                Ps[ty * 4 + i][tx * 2 + jj] = p[i][jj];
        __syncthreads();

        #pragma unroll 4
        for (int c = 0; c < 32; c++) {
            float pa[4], va[4];
            #pragma unroll
            for (int i = 0; i < 4; i++) pa[i] = Ps[ty * 4 + i][c];
            #pragma unroll
            for (int j = 0; j < 4; j++) va[j] = Vt[tx * 4 + j][c];
            #pragma unroll
            for (int i = 0; i < 4; i++)
                #pragma unroll
                for (int j = 0; j < 4; j++)
                    o[i][j] = fmaf(pa[i], va[j], o[i][j]);
        }
    }

    const int b = bh >> 4, h = bh & 15;
    #pragma unroll
    for (int i = 0; i < 4; i++) {
        const float inv = 1.f / l_i[i];
        const int qr = qi * 64 + ty * 4 + i;
        float* dst = g_ao + ((size_t)(b * S_ + qr)) * E_ + h * 64 + tx * 4;
        #pragma unroll
        for (int j = 0; j < 4; j++) dst[j] = o[i][j] * inv;
    }
}

}  // namespace

extern "C" void kernel_launch(void* const* d_in, const int* in_sizes, int n_in,
                              void* d_out, int out_size)
{
    (void)out_size;
    InArgs a;
    a.n = (n_in < 8) ? n_in : 8;
    for (int i = 0; i < 8; i++) {
        a.p[i]  = (i < a.n) ? (const float*)d_in[i] : nullptr;
        a.sz[i] = (i < a.n) ? (long long)in_sizes[i] : 0;
    }

    // 0) Identify inputs on-device from sizes + data statistics
    classify_kernel<<<1, 256>>>(a);

    // 1) QKV GEMM (tf32 tensor cores) with fused bias + scatter into [b,h,s,d]
    {
        dim3 grid(3 * E_ / 128, MROWS / 128);
        tf32_gemm_kernel<3 * E_, E_, true><<<grid, 256>>>(nullptr);
    }
    // 2) Causal flash attention
    {
        dim3 grid(S_ / 64, B_ * H_);
        flash_attn_kernel<<<grid, 256>>>();
    }
    // 3) Output projection (tf32 tensor cores)
    {
        dim3 grid(E_ / 128, MROWS / 128);
        tf32_gemm_kernel<E_, E_, false><<<grid, 256>>>((float*)d_out);
    }
}

// round 7
// speedup vs baseline: 1.8682x; 1.4002x over previous
#include <cuda_runtime.h>
#include <math.h>
#include <stdint.h>

namespace {

constexpr int B_ = 2;
constexpr int S_ = 2048;
constexpr int H_ = 16;
constexpr int D_ = 64;
constexpr int E_ = 1024;
constexpr int MROWS = B_ * S_;   // 4096

// Scratch (device globals: allocation-free per harness rules)
__device__ float g_q[(size_t)B_ * H_ * S_ * D_];   // [b,h,s,d]
__device__ float g_k[(size_t)B_ * H_ * S_ * D_];
__device__ float g_v[(size_t)B_ * H_ * S_ * D_];
__device__ float g_ao[(size_t)MROWS * E_];          // [b,s,e] attention output

// Input pointers resolved ON DEVICE by the classifier kernel.
__device__ const float* g_in_x;
__device__ const float* g_in_qkv_w;
__device__ const float* g_in_qkv_b;
__device__ const float* g_in_proj_w;
__device__ const float* g_in_proj_b;

struct InArgs {
    const float* p[8];
    long long    sz[8];
    int          n;
};

// ---------------------------------------------------------------------------
// Classifier (UNCHANGED): identify inputs by size rank + data statistics.
// ---------------------------------------------------------------------------
__global__ __launch_bounds__(256)
void classify_kernel(InArgs a)
{
    __shared__ float red[256];
    __shared__ float msq[8];
    const int tid = threadIdx.x;

    for (int c = 0; c < a.n; c++) {
        float s = 0.f;
        #pragma unroll
        for (int i = tid; i < 2048; i += 256) {
            const float v = a.p[c][i];
            s += v * v;
        }
        red[tid] = s;
        __syncthreads();
        for (int st = 128; st; st >>= 1) {
            if (tid < st) red[tid] += red[tid + st];
            __syncthreads();
        }
        if (tid == 0) msq[c] = red[0] * (1.f / 2048.f);
        __syncthreads();
    }

    if (tid == 0) {
        int ord[8];
        for (int i = 0; i < a.n; i++) ord[i] = i;
        for (int i = 1; i < a.n; i++) {
            const int o = ord[i];
            const long long s = a.sz[o];
            int j = i - 1;
            while (j >= 0 && a.sz[ord[j]] > s) { ord[j + 1] = ord[j]; j--; }
            ord[j + 1] = o;
        }
        g_in_proj_b = a.p[ord[0]];
        g_in_qkv_b  = a.p[ord[1]];

        int xi = -1;
        for (int r = 2; r < a.n; r++) {
            const float m = msq[ord[r]];
            if (m > 0.3f && m < 3.f) { xi = ord[r]; break; }
        }
        int w0 = -1, w1 = -1;
        for (int r = 2; r < a.n; r++) {
            if (ord[r] == xi) continue;
            if (w0 < 0) { w0 = ord[r]; continue; }
            if (w1 < 0) { w1 = ord[r]; break; }
        }
        g_in_proj_w = a.p[w0];
        g_in_qkv_w  = a.p[w1];
        if (xi < 0) xi = (a.n >= 5) ? ord[4] : ord[a.n - 1];
        g_in_x = a.p[xi];
    }
}

__device__ __forceinline__ uint32_t f2tf32(float f) {
    uint32_t u;
    asm("cvt.rna.tf32.f32 %0, %1;" : "=r"(u) : "f"(f));
    return u;
}

// Fast exp on FMA/ALU pipes (no MUFU): 2^t via range reduction + poly.
// Valid for x <= 0 (clamped at -87); rel err ~2e-7.
__device__ __forceinline__ float fexp(float x) {
    x = fmaxf(x, -87.0f);
    const float t = x * 1.4426950408889634f;
    const int   ei = __float2int_rd(t);
    const float f  = t - (float)ei;
    float p = 1.535336188319500e-4f;
    p = fmaf(p, f, 1.339887440266574e-3f);
    p = fmaf(p, f, 9.618437357674640e-3f);
    p = fmaf(p, f, 5.550332471162809e-2f);
    p = fmaf(p, f, 2.402264791363012e-1f);
    p = fmaf(p, f, 6.931472028550421e-1f);
    p = fmaf(p, f, 1.0f);
    return __uint_as_float(__float_as_uint(p) + ((uint32_t)ei << 23));
}

__device__ __forceinline__ void mma_tf32(float c[4], const uint32_t a[4],
                                         uint32_t b0, uint32_t b1) {
    asm volatile(
        "mma.sync.aligned.m16n8k8.row.col.f32.tf32.tf32.f32 "
        "{%0,%1,%2,%3}, {%4,%5,%6,%7}, {%8,%9}, {%0,%1,%2,%3};"
        : "+f"(c[0]), "+f"(c[1]), "+f"(c[2]), "+f"(c[3])
        : "r"(a[0]), "r"(a[1]), "r"(a[2]), "r"(a[3]), "r"(b0), "r"(b1));
}

// ---------------------------------------------------------------------------
// tf32 tensor-core GEMM (UNCHANGED from passing round 6).
// ---------------------------------------------------------------------------
template <int N, int K, bool QKV>
__global__ __launch_bounds__(256)
void tf32_gemm_kernel(float* __restrict__ C)
{
    const float* A    = QKV ? g_in_x     : g_ao;
    const float* W    = QKV ? g_in_qkv_w : g_in_proj_w;
    const float* bias = QKV ? g_in_qkv_b : g_in_proj_b;

    constexpr int BM = 128, BN = 128, BK = 32, PAD = 133;
    __shared__ uint32_t As[BK * PAD];
    __shared__ uint32_t Bs[BK * PAD];

    const int tid  = threadIdx.x;
    const int warp = tid >> 5;
    const int lane = tid & 31;
    const int wm = (warp & 1) * 64;
    const int wn = (warp >> 1) * 32;

    const int rowA = blockIdx.y * BM;
    const int colB = blockIdx.x * BN;
    const float* Ab = A + (size_t)rowA * K;
    const float* Wb = W + (size_t)colB * K;

    const int lr  = tid >> 3;
    const int lc4 = (tid & 7) << 2;

    float acc[4][4][4] = {};

    const int qr = lane >> 2;
    const int qk = lane & 3;

    for (int kt = 0; kt < K; kt += BK) {
        #pragma unroll
        for (int it = 0; it < 4; it++) {
            const int r = lr + it * 32;
            float4 av = *reinterpret_cast<const float4*>(Ab + (size_t)r * K + kt + lc4);
            float4 bv = *reinterpret_cast<const float4*>(Wb + (size_t)r * K + kt + lc4);
            As[(lc4 + 0) * PAD + r] = f2tf32(av.x);
            As[(lc4 + 1) * PAD + r] = f2tf32(av.y);
            As[(lc4 + 2) * PAD + r] = f2tf32(av.z);
            As[(lc4 + 3) * PAD + r] = f2tf32(av.w);
            Bs[(lc4 + 0) * PAD + r] = f2tf32(bv.x);
            Bs[(lc4 + 1) * PAD + r] = f2tf32(bv.y);
            Bs[(lc4 + 2) * PAD + r] = f2tf32(bv.z);
            Bs[(lc4 + 3) * PAD + r] = f2tf32(bv.w);
        }
        __syncthreads();

        #pragma unroll
        for (int ks = 0; ks < 4; ks++) {
            const int k0 = ks * 8;
            uint32_t af[4][4], bf[4][2];
            #pragma unroll
            for (int mt = 0; mt < 4; mt++) {
                const int m0 = wm + mt * 16;
                af[mt][0] = As[(k0 + qk    ) * PAD + m0 + qr    ];
                af[mt][1] = As[(k0 + qk    ) * PAD + m0 + qr + 8];
                af[mt][2] = As[(k0 + qk + 4) * PAD + m0 + qr    ];
                af[mt][3] = As[(k0 + qk + 4) * PAD + m0 + qr + 8];
            }
            #pragma unroll
            for (int nt = 0; nt < 4; nt++) {
                const int n0 = wn + nt * 8;
                bf[nt][0] = Bs[(k0 + qk    ) * PAD + n0 + qr];
                bf[nt][1] = Bs[(k0 + qk + 4) * PAD + n0 + qr];
            }
            #pragma unroll
            for (int mt = 0; mt < 4; mt++)
                #pragma unroll
                for (int nt = 0; nt < 4; nt++)
                    mma_tf32(acc[mt][nt], af[mt], bf[nt][0], bf[nt][1]);
        }
        __syncthreads();
    }

    #pragma unroll
    for (int mt = 0; mt < 4; mt++) {
        #pragma unroll
        for (int nt = 0; nt < 4; nt++) {
            #pragma unroll
            for (int rg = 0; rg < 4; rg++) {
                const int m = rowA + wm + mt * 16 + qr + ((rg >> 1) << 3);
                const int n = colB + wn + nt * 8 + (qk << 1) + (rg & 1);
                const float v = acc[mt][nt][rg] + bias[n];
                if (QKV) {
                    const int which = n >> 10;
                    float* dst = (which == 0) ? g_q : (which == 1) ? g_k : g_v;
                    const int b = m >> 11, s = m & (S_ - 1);
                    const int c = n & (E_ - 1);
                    const int h = c >> 6, d = c & (D_ - 1);
                    dst[(((size_t)(b * H_ + h)) * S_ + s) * D_ + d] = v;
                } else {
                    C[(size_t)m * N + n] = v;
                }
            }
        }
    }
}

// ---------------------------------------------------------------------------
// Tensor-core causal flash attention (tf32 mma, FMA-pipe exp).
// Br=64, Bc=64, D=64. 128 threads = 4 warps; warp w owns q-rows w*16..w*16+15.
// QK^T: A = Q split hi/lo (regs, loop-invariant), B = K (smem tf32).
// PV  : A = P split hi/lo (via quad shuffles from S c-frags), B = V (smem tf32).
// ---------------------------------------------------------------------------
constexpr int KLD = 68;   // Ks row pitch (uint32) -> b-frag reads conflict-free
constexpr int VLD = 72;   // Vs row pitch (uint32) -> b-frag reads conflict-free

__global__ __launch_bounds__(128)
void flash_attn_mma_kernel()
{
    const int qi = blockIdx.x;   // q tile, 0..31
    const int bh = blockIdx.y;   // 0..31 = b*H + h
    const float* Qg = g_q + (size_t)bh * S_ * D_;
    const float* Kg = g_k + (size_t)bh * S_ * D_;
    const float* Vg = g_v + (size_t)bh * S_ * D_;

    __shared__ uint32_t Ks[64 * KLD];   // [kv][d] tf32 bits
    __shared__ uint32_t Vs[64 * VLD];   // [kv][d] tf32 bits

    const int tid  = threadIdx.x;
    const int warp = tid >> 5;
    const int lane = tid & 31;
    const int qr = lane >> 2;    // 0..7
    const int qk = lane & 3;     // 0..3
    const int qrow0 = qi * 64 + warp * 16 + qr;   // thread's row A (row B = +8)

    // Preload Q a-frags (scaled, split hi/lo). Loop-invariant across kv tiles.
    uint32_t qa_hi[8][4], qa_lo[8][4];
    #pragma unroll
    for (int ks = 0; ks < 8; ks++) {
        const int c0 = ks * 8 + qk, c1 = c0 + 4;
        const float vals[4] = {
            Qg[(size_t)qrow0 * D_ + c0]       * 0.125f,
            Qg[(size_t)(qrow0 + 8) * D_ + c0] * 0.125f,
            Qg[(size_t)qrow0 * D_ + c1]       * 0.125f,
            Qg[(size_t)(qrow0 + 8) * D_ + c1] * 0.125f };
        #pragma unroll
        for (int t = 0; t < 4; t++) {
            const uint32_t hb = f2tf32(vals[t]);
            qa_hi[ks][t] = hb;
            qa_lo[ks][t] = f2tf32(vals[t] - __uint_as_float(hb));
        }
    }

    float o[8][4] = {};
    float m0 = -1e30f, m1 = -1e30f, l0 = 0.f, l1 = 0.f;

    // Fill indices: thread covers row tid>>1, 32 cols starting at (tid&1)*32
    const int frow = tid >> 1;
    const int fcol = (tid & 1) * 32;

    for (int jt = 0; jt <= qi; jt++) {
        const int kv0 = jt * 64;
        __syncthreads();
        #pragma unroll
        for (int t = 0; t < 8; t++) {
            const int c = fcol + t * 4;
            float4 kv4 = *reinterpret_cast<const float4*>(Kg + (size_t)(kv0 + frow) * D_ + c);
            float4 vv4 = *reinterpret_cast<const float4*>(Vg + (size_t)(kv0 + frow) * D_ + c);
            Ks[frow * KLD + c + 0] = f2tf32(kv4.x);
            Ks[frow * KLD + c + 1] = f2tf32(kv4.y);
            Ks[frow * KLD + c + 2] = f2tf32(kv4.z);
            Ks[frow * KLD + c + 3] = f2tf32(kv4.w);
            Vs[frow * VLD + c + 0] = f2tf32(vv4.x);
            Vs[frow * VLD + c + 1] = f2tf32(vv4.y);
            Vs[frow * VLD + c + 2] = f2tf32(vv4.z);
            Vs[frow * VLD + c + 3] = f2tf32(vv4.w);
        }
        __syncthreads();

        // ---- S = (Q*scale) @ K^T, split-Q (2 mma per frag pair) ----
        float sc[8][4] = {};
        #pragma unroll
        for (int ks = 0; ks < 8; ks++) {
            const int k0 = ks * 8;
            #pragma unroll
            for (int nt = 0; nt < 8; nt++) {
                const uint32_t b0 = Ks[(nt * 8 + qr) * KLD + k0 + qk];
                const uint32_t b1 = Ks[(nt * 8 + qr) * KLD + k0 + qk + 4];
                mma_tf32(sc[nt], qa_hi[ks], b0, b1);
                mma_tf32(sc[nt], qa_lo[ks], b0, b1);
            }
        }

        // ---- causal mask on the diagonal tile ----
        if (jt == qi) {
            #pragma unroll
            for (int nt = 0; nt < 8; nt++)
                #pragma unroll
                for (int rg = 0; rg < 4; rg++) {
                    const int kv = kv0 + nt * 8 + (qk << 1) + (rg & 1);
                    const int qrow = qrow0 + ((rg >> 1) << 3);
                    if (kv > qrow) sc[nt][rg] = -1e30f;
                }
        }

        // ---- online softmax (rows qr and qr+8), exp on FMA pipe ----
        {
            float mx = -1e30f;
            #pragma unroll
            for (int nt = 0; nt < 8; nt++) mx = fmaxf(mx, fmaxf(sc[nt][0], sc[nt][1]));
            mx = fmaxf(mx, __shfl_xor_sync(0xffffffffu, mx, 1));
            mx = fmaxf(mx, __shfl_xor_sync(0xffffffffu, mx, 2));
            const float mn = fmaxf(m0, mx);
            const float alpha = fexp(m0 - mn);
            m0 = mn;
            float sum = 0.f;
            #pragma unroll
            for (int nt = 0; nt < 8; nt++) {
                sc[nt][0] = fexp(sc[nt][0] - mn);
                sc[nt][1] = fexp(sc[nt][1] - mn);
                sum += sc[nt][0] + sc[nt][1];
            }
            sum += __shfl_xor_sync(0xffffffffu, sum, 1);
            sum += __shfl_xor_sync(0xffffffffu, sum, 2);
            l0 = l0 * alpha + sum;
            #pragma unroll
            for (int nt = 0; nt < 8; nt++) { o[nt][0] *= alpha; o[nt][1] *= alpha; }
        }
        {
            float mx = -1e30f;
            #pragma unroll
            for (int nt = 0; nt < 8; nt++) mx = fmaxf(mx, fmaxf(sc[nt][2], sc[nt][3]));
            mx = fmaxf(mx, __shfl_xor_sync(0xffffffffu, mx, 1));
            mx = fmaxf(mx, __shfl_xor_sync(0xffffffffu, mx, 2));
            const float mn = fmaxf(m1, mx);
            const float alpha = fexp(m1 - mn);
            m1 = mn;
            float sum = 0.f;
            #pragma unroll
            for (int nt = 0; nt < 8; nt++) {
                sc[nt][2] = fexp(sc[nt][2] - mn);
                sc[nt][3] = fexp(sc[nt][3] - mn);
                sum += sc[nt][2] + sc[nt][3];
            }
            sum += __shfl_xor_sync(0xffffffffu, sum, 1);
            sum += __shfl_xor_sync(0xffffffffu, sum, 2);
            l1 = l1 * alpha + sum;
            #pragma unroll
            for (int nt = 0; nt < 8; nt++) { o[nt][2] *= alpha; o[nt][3] *= alpha; }
        }

        // ---- O += P @ V : P c-frags -> a-frags via quad shuffles, split-P ----
        #pragma unroll
        for (int ks = 0; ks < 8; ks++) {
            const int Ls  = (qr << 2) + (qk >> 1);  // src lane for pos = qk
            const int Ls2 = Ls + 2;                 // src lane for pos = qk+4
            const bool oddp = (qk & 1);

            const float t00 = __shfl_sync(0xffffffffu, sc[ks][0], Ls);
            const float t01 = __shfl_sync(0xffffffffu, sc[ks][1], Ls);
            const float t20 = __shfl_sync(0xffffffffu, sc[ks][2], Ls);
            const float t21 = __shfl_sync(0xffffffffu, sc[ks][3], Ls);
            const float u00 = __shfl_sync(0xffffffffu, sc[ks][0], Ls2);
            const float u01 = __shfl_sync(0xffffffffu, sc[ks][1], Ls2);
            const float u20 = __shfl_sync(0xffffffffu, sc[ks][2], Ls2);
            const float u21 = __shfl_sync(0xffffffffu, sc[ks][3], Ls2);

            const float af[4] = {
                oddp ? t01 : t00,   // P[qr  ][8ks+qk]
                oddp ? t21 : t20,   // P[qr+8][8ks+qk]
                oddp ? u01 : u00,   // P[qr  ][8ks+qk+4]
                oddp ? u21 : u20 }; // P[qr+8][8ks+qk+4]

            uint32_t pa_hi[4], pa_lo[4];
            #pragma unroll
            for (int t = 0; t < 4; t++) {
                const uint32_t hb = f2tf32(af[t]);
                pa_hi[t] = hb;
                pa_lo[t] = f2tf32(af[t] - __uint_as_float(hb));
            }

            const int k0 = ks * 8;
            #pragma unroll
            for (int nt = 0; nt < 8; nt++) {
                const uint32_t b0 = Vs[(k0 + qk) * VLD + nt * 8 + qr];
                const uint32_t b1 = Vs[(k0 + qk + 4) * VLD + nt * 8 + qr];
                mma_tf32(o[nt], pa_hi, b0, b1);
                mma_tf32(o[nt], pa_lo, b0, b1);
            }
        }
    }

    // ---- finalize: divide by l, write g_ao[b, s, h*64 + d] ----
    const int b = bh >> 4, h = bh & 15;
    const float inv0 = 1.f / l0, inv1 = 1.f / l1;
    #pragma unroll
    for (int nt = 0; nt < 8; nt++) {
        const int d0 = nt * 8 + (qk << 1);
        float2 r0 = { o[nt][0] * inv0, o[nt][1] * inv0 };
        float2 r1 = { o[nt][2] * inv1, o[nt][3] * inv1 };
        *reinterpret_cast<float2*>(g_ao + ((size_t)(b * S_ + qrow0)) * E_ + h * 64 + d0) = r0;
        *reinterpret_cast<float2*>(g_ao + ((size_t)(b * S_ + qrow0 + 8)) * E_ + h * 64 + d0) = r1;
    }
}

}  // namespace

extern "C" void kernel_launch(void* const* d_in, const int* in_sizes, int n_in,
                              void* d_out, int out_size)
{
    (void)out_size;
    InArgs a;
    a.n = (n_in < 8) ? n_in : 8;
    for (int i = 0; i < 8; i++) {
        a.p[i]  = (i < a.n) ? (const float*)d_in[i] : nullptr;
        a.sz[i] = (i < a.n) ? (long long)in_sizes[i] : 0;
    }

    // 0) Identify inputs on-device from sizes + data statistics
    classify_kernel<<<1, 256>>>(a);

    // 1) QKV GEMM (tf32 tensor cores) with fused bias + scatter into [b,h,s,d]
    {
        dim3 grid(3 * E_ / 128, MROWS / 128);
        tf32_gemm_kernel<3 * E_, E_, true><<<grid, 256>>>(nullptr);
    }
    // 2) Causal flash attention (tensor cores)
    {
        dim3 grid(S_ / 64, B_ * H_);
        flash_attn_mma_kernel<<<grid, 128>>>();
    }
    // 3) Output projection (tf32 tensor cores)
    {
        dim3 grid(E_ / 128, MROWS / 128);
        tf32_gemm_kernel<E_, E_, false><<<grid, 256>>>((float*)d_out);
    }
}

// round 8
// speedup vs baseline: 2.1629x; 1.1578x over previous
#include <cuda_runtime.h>
#include <math.h>
#include <stdint.h>

namespace {

constexpr int B_ = 2;
constexpr int S_ = 2048;
constexpr int H_ = 16;
constexpr int D_ = 64;
constexpr int E_ = 1024;
constexpr int MROWS = B_ * S_;   // 4096

// Scratch (device globals: allocation-free per harness rules)
__device__ float g_q[(size_t)B_ * H_ * S_ * D_];   // [b,h,s,d]
__device__ float g_k[(size_t)B_ * H_ * S_ * D_];
__device__ float g_v[(size_t)B_ * H_ * S_ * D_];
__device__ float g_ao[(size_t)MROWS * E_];          // [b,s,e] attention output

// Input pointers resolved ON DEVICE by the classifier kernel.
__device__ const float* g_in_x;
__device__ const float* g_in_qkv_w;
__device__ const float* g_in_qkv_b;
__device__ const float* g_in_proj_w;
__device__ const float* g_in_proj_b;

struct InArgs {
    const float* p[8];
    long long    sz[8];
    int          n;
};

// ---------------------------------------------------------------------------
// Classifier (UNCHANGED): identify inputs by size rank + data statistics.
// ---------------------------------------------------------------------------
__global__ __launch_bounds__(256)
void classify_kernel(InArgs a)
{
    __shared__ float red[256];
    __shared__ float msq[8];
    const int tid = threadIdx.x;

    for (int c = 0; c < a.n; c++) {
        float s = 0.f;
        #pragma unroll
        for (int i = tid; i < 2048; i += 256) {
            const float v = a.p[c][i];
            s += v * v;
        }
        red[tid] = s;
        __syncthreads();
        for (int st = 128; st; st >>= 1) {
            if (tid < st) red[tid] += red[tid + st];
            __syncthreads();
        }
        if (tid == 0) msq[c] = red[0] * (1.f / 2048.f);
        __syncthreads();
    }

    if (tid == 0) {
        int ord[8];
        for (int i = 0; i < a.n; i++) ord[i] = i;
        for (int i = 1; i < a.n; i++) {
            const int o = ord[i];
            const long long s = a.sz[o];
            int j = i - 1;
            while (j >= 0 && a.sz[ord[j]] > s) { ord[j + 1] = ord[j]; j--; }
            ord[j + 1] = o;
        }
        g_in_proj_b = a.p[ord[0]];
        g_in_qkv_b  = a.p[ord[1]];

        int xi = -1;
        for (int r = 2; r < a.n; r++) {
            const float m = msq[ord[r]];
            if (m > 0.3f && m < 3.f) { xi = ord[r]; break; }
        }
        int w0 = -1, w1 = -1;
        for (int r = 2; r < a.n; r++) {
            if (ord[r] == xi) continue;
            if (w0 < 0) { w0 = ord[r]; continue; }
            if (w1 < 0) { w1 = ord[r]; break; }
        }
        g_in_proj_w = a.p[w0];
        g_in_qkv_w  = a.p[w1];
        if (xi < 0) xi = (a.n >= 5) ? ord[4] : ord[a.n - 1];
        g_in_x = a.p[xi];
    }
}

__device__ __forceinline__ uint32_t f2tf32(float f) {
    uint32_t u;
    asm("cvt.rna.tf32.f32 %0, %1;" : "=r"(u) : "f"(f));
    return u;
}

// Fast exp on FMA/ALU pipes (no MUFU). Valid for x <= 0 (clamped at -87).
__device__ __forceinline__ float fexp(float x) {
    x = fmaxf(x, -87.0f);
    const float t = x * 1.4426950408889634f;
    const int   ei = __float2int_rd(t);
    const float f  = t - (float)ei;
    float p = 1.535336188319500e-4f;
    p = fmaf(p, f, 1.339887440266574e-3f);
    p = fmaf(p, f, 9.618437357674640e-3f);
    p = fmaf(p, f, 5.550332471162809e-2f);
    p = fmaf(p, f, 2.402264791363012e-1f);
    p = fmaf(p, f, 6.931472028550421e-1f);
    p = fmaf(p, f, 1.0f);
    return __uint_as_float(__float_as_uint(p) + ((uint32_t)ei << 23));
}

__device__ __forceinline__ void mma_tf32(float c[4], const uint32_t a[4],
                                         uint32_t b0, uint32_t b1) {
    asm volatile(
        "mma.sync.aligned.m16n8k8.row.col.f32.tf32.tf32.f32 "
        "{%0,%1,%2,%3}, {%4,%5,%6,%7}, {%8,%9}, {%0,%1,%2,%3};"
        : "+f"(c[0]), "+f"(c[1]), "+f"(c[2]), "+f"(c[3])
        : "r"(a[0]), "r"(a[1]), "r"(a[2]), "r"(a[3]), "r"(b0), "r"(b1));
}

// ---------------------------------------------------------------------------
// tf32 tensor-core GEMM with register-prefetch pipelining.
// Block 128x128, BK=16, 256 threads = 8 warps (2m x 4n), warp tile 64x32.
// Global loads for tile i+1 are issued before computing tile i (latency hidden).
// PAD=140 -> all fragment LDS reads conflict-free; STS 2-way.
// ---------------------------------------------------------------------------
template <int N, int K, bool QKV>
__global__ __launch_bounds__(256, 2)
void tf32_gemm_kernel(float* __restrict__ C)
{
    const float* A    = QKV ? g_in_x     : g_ao;
    const float* W    = QKV ? g_in_qkv_w : g_in_proj_w;
    const float* bias = QKV ? g_in_qkv_b : g_in_proj_b;

    constexpr int BM = 128, BN = 128, BK = 16, PADR = 140;
    __shared__ uint32_t As[BK * PADR];
    __shared__ uint32_t Bs[BK * PADR];

    const int tid  = threadIdx.x;
    const int warp = tid >> 5;
    const int lane = tid & 31;
    const int wm = (warp & 1) * 64;
    const int wn = (warp >> 1) * 32;
    const int qr = lane >> 2;
    const int qk = lane & 3;

    const int rowA = blockIdx.y * BM;
    const int colB = blockIdx.x * BN;
    const float* Ab = A + (size_t)rowA * K;
    const float* Wb = W + (size_t)colB * K;

    const int lr  = tid >> 2;           // 0..63
    const int lc4 = (tid & 3) << 2;     // 0,4,8,12

    // Prologue: prefetch tile 0
    float4 pa0 = *reinterpret_cast<const float4*>(Ab + (size_t)lr * K + lc4);
    float4 pa1 = *reinterpret_cast<const float4*>(Ab + (size_t)(lr + 64) * K + lc4);
    float4 pb0 = *reinterpret_cast<const float4*>(Wb + (size_t)lr * K + lc4);
    float4 pb1 = *reinterpret_cast<const float4*>(Wb + (size_t)(lr + 64) * K + lc4);

    float acc[4][4][4] = {};

    for (int kt = 0; kt < K; kt += BK) {
        // Store current tile (cvt to tf32), transposed [k][m]
        As[(lc4 + 0) * PADR + lr     ] = f2tf32(pa0.x);
        As[(lc4 + 1) * PADR + lr     ] = f2tf32(pa0.y);
        As[(lc4 + 2) * PADR + lr     ] = f2tf32(pa0.z);
        As[(lc4 + 3) * PADR + lr     ] = f2tf32(pa0.w);
        As[(lc4 + 0) * PADR + lr + 64] = f2tf32(pa1.x);
        As[(lc4 + 1) * PADR + lr + 64] = f2tf32(pa1.y);
        As[(lc4 + 2) * PADR + lr + 64] = f2tf32(pa1.z);
        As[(lc4 + 3) * PADR + lr + 64] = f2tf32(pa1.w);
        Bs[(lc4 + 0) * PADR + lr     ] = f2tf32(pb0.x);
        Bs[(lc4 + 1) * PADR + lr     ] = f2tf32(pb0.y);
        Bs[(lc4 + 2) * PADR + lr     ] = f2tf32(pb0.z);
        Bs[(lc4 + 3) * PADR + lr     ] = f2tf32(pb0.w);
        Bs[(lc4 + 0) * PADR + lr + 64] = f2tf32(pb1.x);
        Bs[(lc4 + 1) * PADR + lr + 64] = f2tf32(pb1.y);
        Bs[(lc4 + 2) * PADR + lr + 64] = f2tf32(pb1.z);
        Bs[(lc4 + 3) * PADR + lr + 64] = f2tf32(pb1.w);
        __syncthreads();

        // Prefetch NEXT tile (overlaps with the mma compute below)
        if (kt + BK < K) {
            const int kn = kt + BK + lc4;
            pa0 = *reinterpret_cast<const float4*>(Ab + (size_t)lr * K + kn);
            pa1 = *reinterpret_cast<const float4*>(Ab + (size_t)(lr + 64) * K + kn);
            pb0 = *reinterpret_cast<const float4*>(Wb + (size_t)lr * K + kn);
            pb1 = *reinterpret_cast<const float4*>(Wb + (size_t)(lr + 64) * K + kn);
        }

        #pragma unroll
        for (int ks = 0; ks < 2; ks++) {
            const int k0 = ks * 8;
            uint32_t af[4][4], bf[4][2];
            #pragma unroll
            for (int mt = 0; mt < 4; mt++) {
                const int m0 = wm + mt * 16;
                af[mt][0] = As[(k0 + qk    ) * PADR + m0 + qr    ];
                af[mt][1] = As[(k0 + qk    ) * PADR + m0 + qr + 8];
                af[mt][2] = As[(k0 + qk + 4) * PADR + m0 + qr    ];
                af[mt][3] = As[(k0 + qk + 4) * PADR + m0 + qr + 8];
            }
            #pragma unroll
            for (int nt = 0; nt < 4; nt++) {
                const int n0 = wn + nt * 8;
                bf[nt][0] = Bs[(k0 + qk    ) * PADR + n0 + qr];
                bf[nt][1] = Bs[(k0 + qk + 4) * PADR + n0 + qr];
            }
            #pragma unroll
            for (int mt = 0; mt < 4; mt++)
                #pragma unroll
                for (int nt = 0; nt < 4; nt++)
                    mma_tf32(acc[mt][nt], af[mt], bf[nt][0], bf[nt][1]);
        }
        __syncthreads();
    }

    #pragma unroll
    for (int mt = 0; mt < 4; mt++) {
        #pragma unroll
        for (int nt = 0; nt < 4; nt++) {
            #pragma unroll
            for (int rg = 0; rg < 4; rg++) {
                const int m = rowA + wm + mt * 16 + qr + ((rg >> 1) << 3);
                const int n = colB + wn + nt * 8 + (qk << 1) + (rg & 1);
                const float v = acc[mt][nt][rg] + bias[n];
                if (QKV) {
                    const int which = n >> 10;
                    float* dst = (which == 0) ? g_q : (which == 1) ? g_k : g_v;
                    const int b = m >> 11, s = m & (S_ - 1);
                    const int c = n & (E_ - 1);
                    const int h = c >> 6, d = c & (D_ - 1);
                    dst[(((size_t)(b * H_ + h)) * S_ + s) * D_ + d] = v;
                } else {
                    C[(size_t)m * N + n] = v;
                }
            }
        }
    }
}

// ---------------------------------------------------------------------------
// Tensor-core causal flash attention (tf32 mma, FMA-pipe exp).
// Br=64, Bc=64, D=64. 128 threads = 4 warps.
// QK^T: Q split hi/lo (loop-invariant regs). PV: single-tf32 P (split dropped:
// P in [0,1], rounding adds ~1e-5 rel — negligible vs existing 6e-4).
// ---------------------------------------------------------------------------
constexpr int KLD = 68;
constexpr int VLD = 72;

__global__ __launch_bounds__(128)
void flash_attn_mma_kernel()
{
    const int qi = blockIdx.x;
    const int bh = blockIdx.y;
    const float* Qg = g_q + (size_t)bh * S_ * D_;
    const float* Kg = g_k + (size_t)bh * S_ * D_;
    const float* Vg = g_v + (size_t)bh * S_ * D_;

    __shared__ uint32_t Ks[64 * KLD];
    __shared__ uint32_t Vs[64 * VLD];

    const int tid  = threadIdx.x;
    const int warp = tid >> 5;
    const int lane = tid & 31;
    const int qr = lane >> 2;
    const int qk = lane & 3;
    const int qrow0 = qi * 64 + warp * 16 + qr;

    uint32_t qa_hi[8][4], qa_lo[8][4];
    #pragma unroll
    for (int ks = 0; ks < 8; ks++) {
        const int c0 = ks * 8 + qk, c1 = c0 + 4;
        const float vals[4] = {
            Qg[(size_t)qrow0 * D_ + c0]       * 0.125f,
            Qg[(size_t)(qrow0 + 8) * D_ + c0] * 0.125f,
            Qg[(size_t)qrow0 * D_ + c1]       * 0.125f,
            Qg[(size_t)(qrow0 + 8) * D_ + c1] * 0.125f };
        #pragma unroll
        for (int t = 0; t < 4; t++) {
            const uint32_t hb = f2tf32(vals[t]);
            qa_hi[ks][t] = hb;
            qa_lo[ks][t] = f2tf32(vals[t] - __uint_as_float(hb));
        }
    }

    float o[8][4] = {};
    float m0 = -1e30f, m1 = -1e30f, l0 = 0.f, l1 = 0.f;

    const int frow = tid >> 1;
    const int fcol = (tid & 1) * 32;

    for (int jt = 0; jt <= qi; jt++) {
        const int kv0 = jt * 64;
        __syncthreads();
        #pragma unroll
        for (int t = 0; t < 8; t++) {
            const int c = fcol + t * 4;
            float4 kv4 = *reinterpret_cast<const float4*>(Kg + (size_t)(kv0 + frow) * D_ + c);
            float4 vv4 = *reinterpret_cast<const float4*>(Vg + (size_t)(kv0 + frow) * D_ + c);
            Ks[frow * KLD + c + 0] = f2tf32(kv4.x);
            Ks[frow * KLD + c + 1] = f2tf32(kv4.y);
            Ks[frow * KLD + c + 2] = f2tf32(kv4.z);
            Ks[frow * KLD + c + 3] = f2tf32(kv4.w);
            Vs[frow * VLD + c + 0] = f2tf32(vv4.x);
            Vs[frow * VLD + c + 1] = f2tf32(vv4.y);
            Vs[frow * VLD + c + 2] = f2tf32(vv4.z);
            Vs[frow * VLD + c + 3] = f2tf32(vv4.w);
        }
        __syncthreads();

        float sc[8][4] = {};
        #pragma unroll
        for (int ks = 0; ks < 8; ks++) {
            const int k0 = ks * 8;
            #pragma unroll
            for (int nt = 0; nt < 8; nt++) {
                const uint32_t b0 = Ks[(nt * 8 + qr) * KLD + k0 + qk];
                const uint32_t b1 = Ks[(nt * 8 + qr) * KLD + k0 + qk + 4];
                mma_tf32(sc[nt], qa_hi[ks], b0, b1);
                mma_tf32(sc[nt], qa_lo[ks], b0, b1);
            }
        }

        if (jt == qi) {
            #pragma unroll
            for (int nt = 0; nt < 8; nt++)
                #pragma unroll
                for (int rg = 0; rg < 4; rg++) {
                    const int kv = kv0 + nt * 8 + (qk << 1) + (rg & 1);
                    const int qrow = qrow0 + ((rg >> 1) << 3);
                    if (kv > qrow) sc[nt][rg] = -1e30f;
                }
        }

        {
            float mx = -1e30f;
            #pragma unroll
            for (int nt = 0; nt < 8; nt++) mx = fmaxf(mx, fmaxf(sc[nt][0], sc[nt][1]));
            mx = fmaxf(mx, __shfl_xor_sync(0xffffffffu, mx, 1));
            mx = fmaxf(mx, __shfl_xor_sync(0xffffffffu, mx, 2));
            const float mn = fmaxf(m0, mx);
            const float alpha = fexp(m0 - mn);
            m0 = mn;
            float sum = 0.f;
            #pragma unroll
            for (int nt = 0; nt < 8; nt++) {
                sc[nt][0] = fexp(sc[nt][0] - mn);
                sc[nt][1] = fexp(sc[nt][1] - mn);
                sum += sc[nt][0] + sc[nt][1];
            }
            sum += __shfl_xor_sync(0xffffffffu, sum, 1);
            sum += __shfl_xor_sync(0xffffffffu, sum, 2);
            l0 = l0 * alpha + sum;
            #pragma unroll
            for (int nt = 0; nt < 8; nt++) { o[nt][0] *= alpha; o[nt][1] *= alpha; }
        }
        {
            float mx = -1e30f;
            #pragma unroll
            for (int nt = 0; nt < 8; nt++) mx = fmaxf(mx, fmaxf(sc[nt][2], sc[nt][3]));
            mx = fmaxf(mx, __shfl_xor_sync(0xffffffffu, mx, 1));
            mx = fmaxf(mx, __shfl_xor_sync(0xffffffffu, mx, 2));
            const float mn = fmaxf(m1, mx);
            const float alpha = fexp(m1 - mn);
            m1 = mn;
            float sum = 0.f;
            #pragma unroll
            for (int nt = 0; nt < 8; nt++) {
                sc[nt][2] = fexp(sc[nt][2] - mn);
                sc[nt][3] = fexp(sc[nt][3] - mn);
                sum += sc[nt][2] + sc[nt][3];
            }
            sum += __shfl_xor_sync(0xffffffffu, sum, 1);
            sum += __shfl_xor_sync(0xffffffffu, sum, 2);
            l1 = l1 * alpha + sum;
            #pragma unroll
            for (int nt = 0; nt < 8; nt++) { o[nt][2] *= alpha; o[nt][3] *= alpha; }
        }

        // O += P @ V (single-tf32 P)
        #pragma unroll
        for (int ks = 0; ks < 8; ks++) {
            const int Ls  = (qr << 2) + (qk >> 1);
            const int Ls2 = Ls + 2;
            const bool oddp = (qk & 1);

            const float t00 = __shfl_sync(0xffffffffu, sc[ks][0], Ls);
            const float t01 = __shfl_sync(0xffffffffu, sc[ks][1], Ls);
            const float t20 = __shfl_sync(0xffffffffu, sc[ks][2], Ls);
            const float t21 = __shfl_sync(0xffffffffu, sc[ks][3], Ls);
            const float u00 = __shfl_sync(0xffffffffu, sc[ks][0], Ls2);
            const float u01 = __shfl_sync(0xffffffffu, sc[ks][1], Ls2);
            const float u20 = __shfl_sync(0xffffffffu, sc[ks][2], Ls2);
            const float u21 = __shfl_sync(0xffffffffu, sc[ks][3], Ls2);

            uint32_t pa[4];
            pa[0] = f2tf32(oddp ? t01 : t00);
            pa[1] = f2tf32(oddp ? t21 : t20);
            pa[2] = f2tf32(oddp ? u01 : u00);
            pa[3] = f2tf32(oddp ? u21 : u20);

            const int k0 = ks * 8;
            #pragma unroll
            for (int nt = 0; nt < 8; nt++) {
                const uint32_t b0 = Vs[(k0 + qk) * VLD + nt * 8 + qr];
                const uint32_t b1 = Vs[(k0 + qk + 4) * VLD + nt * 8 + qr];
                mma_tf32(o[nt], pa, b0, b1);
            }
        }
    }

    const int b = bh >> 4, h = bh & 15;
    const float inv0 = 1.f / l0, inv1 = 1.f / l1;
    #pragma unroll
    for (int nt = 0; nt < 8; nt++) {
        const int d0 = nt * 8 + (qk << 1);
        float2 r0 = { o[nt][0] * inv0, o[nt][1] * inv0 };
        float2 r1 = { o[nt][2] * inv1, o[nt][3] * inv1 };
        *reinterpret_cast<float2*>(g_ao + ((size_t)(b * S_ + qrow0)) * E_ + h * 64 + d0) = r0;
        *reinterpret_cast<float2*>(g_ao + ((size_t)(b * S_ + qrow0 + 8)) * E_ + h * 64 + d0) = r1;
    }
}

}  // namespace

extern "C" void kernel_launch(void* const* d_in, const int* in_sizes, int n_in,
                              void* d_out, int out_size)
{
    (void)out_size;
    InArgs a;
    a.n = (n_in < 8) ? n_in : 8;
    for (int i = 0; i < 8; i++) {
        a.p[i]  = (i < a.n) ? (const float*)d_in[i] : nullptr;
        a.sz[i] = (i < a.n) ? (long long)in_sizes[i] : 0;
    }

    classify_kernel<<<1, 256>>>(a);

    {
        dim3 grid(3 * E_ / 128, MROWS / 128);
        tf32_gemm_kernel<3 * E_, E_, true><<<grid, 256>>>(nullptr);
    }
    {
        dim3 grid(S_ / 64, B_ * H_);
        flash_attn_mma_kernel<<<grid, 128>>>();
    }
    {
        dim3 grid(E_ / 128, MROWS / 128);
        tf32_gemm_kernel<E_, E_, false><<<grid, 256>>>((float*)d_out);
    }
}

// round 9
// speedup vs baseline: 2.4566x; 1.1358x over previous
#include <cuda_runtime.h>
#include <math.h>
#include <stdint.h>

namespace {

constexpr int B_ = 2;
constexpr int S_ = 2048;
constexpr int H_ = 16;
constexpr int D_ = 64;
constexpr int E_ = 1024;
constexpr int MROWS = B_ * S_;   // 4096

// Scratch (device globals: allocation-free per harness rules)
__device__ float g_q[(size_t)B_ * H_ * S_ * D_];   // [b,h,s,d] fp32
__device__ float g_k[(size_t)B_ * H_ * S_ * D_];
__device__ float g_v[(size_t)B_ * H_ * S_ * D_];
__device__ float g_ao[(size_t)MROWS * E_];          // [b,s,e] holds TF32 BITS

// Pre-converted tf32 operands
__device__ uint32_t g_xa[(size_t)MROWS * E_];        // x as tf32
__device__ uint32_t g_wqkv[(size_t)3 * E_ * E_];     // qkv_w as tf32
__device__ uint32_t g_wproj[(size_t)E_ * E_];        // proj_w as tf32

// Input pointers resolved ON DEVICE by the classifier kernel.
__device__ const float* g_in_x;
__device__ const float* g_in_qkv_w;
__device__ const float* g_in_qkv_b;
__device__ const float* g_in_proj_w;
__device__ const float* g_in_proj_b;

struct InArgs {
    const float* p[8];
    long long    sz[8];
    int          n;
};

// ---------------------------------------------------------------------------
// Classifier (UNCHANGED): identify inputs by size rank + data statistics.
// ---------------------------------------------------------------------------
__global__ __launch_bounds__(256)
void classify_kernel(InArgs a)
{
    __shared__ float red[256];
    __shared__ float msq[8];
    const int tid = threadIdx.x;

    for (int c = 0; c < a.n; c++) {
        float s = 0.f;
        #pragma unroll
        for (int i = tid; i < 2048; i += 256) {
            const float v = a.p[c][i];
            s += v * v;
        }
        red[tid] = s;
        __syncthreads();
        for (int st = 128; st; st >>= 1) {
            if (tid < st) red[tid] += red[tid + st];
            __syncthreads();
        }
        if (tid == 0) msq[c] = red[0] * (1.f / 2048.f);
        __syncthreads();
    }

    if (tid == 0) {
        int ord[8];
        for (int i = 0; i < a.n; i++) ord[i] = i;
        for (int i = 1; i < a.n; i++) {
            const int o = ord[i];
            const long long s = a.sz[o];
            int j = i - 1;
            while (j >= 0 && a.sz[ord[j]] > s) { ord[j + 1] = ord[j]; j--; }
            ord[j + 1] = o;
        }
        g_in_proj_b = a.p[ord[0]];
        g_in_qkv_b  = a.p[ord[1]];

        int xi = -1;
        for (int r = 2; r < a.n; r++) {
            const float m = msq[ord[r]];
            if (m > 0.3f && m < 3.f) { xi = ord[r]; break; }
        }
        int w0 = -1, w1 = -1;
        for (int r = 2; r < a.n; r++) {
            if (ord[r] == xi) continue;
            if (w0 < 0) { w0 = ord[r]; continue; }
            if (w1 < 0) { w1 = ord[r]; break; }
        }
        g_in_proj_w = a.p[w0];
        g_in_qkv_w  = a.p[w1];
        if (xi < 0) xi = (a.n >= 5) ? ord[4] : ord[a.n - 1];
        g_in_x = a.p[xi];
    }
}

__device__ __forceinline__ uint32_t f2tf32(float f) {
    uint32_t u;
    asm("cvt.rna.tf32.f32 %0, %1;" : "=r"(u) : "f"(f));
    return u;
}

// Pre-convert an operand tensor to tf32 bits. WHICH: 0=x, 1=qkv_w, 2=proj_w.
template <int WHICH, int NELEM>
__global__ __launch_bounds__(256)
void convert_tf32_kernel()
{
    const float* src = (WHICH == 0) ? g_in_x : (WHICH == 1) ? g_in_qkv_w : g_in_proj_w;
    uint32_t*    dst = (WHICH == 0) ? g_xa   : (WHICH == 1) ? g_wqkv    : g_wproj;
    const int stride = gridDim.x * 256;
    for (int i = blockIdx.x * 256 + threadIdx.x; i < NELEM / 4; i += stride) {
        const float4 v = reinterpret_cast<const float4*>(src)[i];
        uint4 o;
        o.x = f2tf32(v.x); o.y = f2tf32(v.y);
        o.z = f2tf32(v.z); o.w = f2tf32(v.w);
        reinterpret_cast<uint4*>(dst)[i] = o;
    }
}

// Fast exp on FMA/ALU pipes (no MUFU). Valid for x <= 0 (clamped at -87).
__device__ __forceinline__ float fexp(float x) {
    x = fmaxf(x, -87.0f);
    const float t = x * 1.4426950408889634f;
    const int   ei = __float2int_rd(t);
    const float f  = t - (float)ei;
    float p = 1.535336188319500e-4f;
    p = fmaf(p, f, 1.339887440266574e-3f);
    p = fmaf(p, f, 9.618437357674640e-3f);
    p = fmaf(p, f, 5.550332471162809e-2f);
    p = fmaf(p, f, 2.402264791363012e-1f);
    p = fmaf(p, f, 6.931472028550421e-1f);
    p = fmaf(p, f, 1.0f);
    return __uint_as_float(__float_as_uint(p) + ((uint32_t)ei << 23));
}

__device__ __forceinline__ void mma_tf32(float c[4], const uint32_t a[4],
                                         uint32_t b0, uint32_t b1) {
    asm volatile(
        "mma.sync.aligned.m16n8k8.row.col.f32.tf32.tf32.f32 "
        "{%0,%1,%2,%3}, {%4,%5,%6,%7}, {%8,%9}, {%0,%1,%2,%3};"
        : "+f"(c[0]), "+f"(c[1]), "+f"(c[2]), "+f"(c[3])
        : "r"(a[0]), "r"(a[1]), "r"(a[2]), "r"(a[3]), "r"(b0), "r"(b1));
}

__device__ __forceinline__ void cp_async16(uint32_t smem_dst, const void* gsrc) {
    asm volatile("cp.async.cg.shared.global [%0], [%1], 16;"
                 :: "r"(smem_dst), "l"(gsrc));
}

// ---------------------------------------------------------------------------
// tf32 tensor-core GEMM, cp.async double-buffered, pre-converted operands.
// Block 128x128, BK=16, 128 threads = 4 warps (2m x 2n), warp tile 64x64.
// SMEM row-major [row][k] with PITCH=20 -> all fragment LDS conflict-free.
// ---------------------------------------------------------------------------
template <int N, int K, bool QKV>
__global__ __launch_bounds__(128, 2)
void tf32_gemm_kernel(float* __restrict__ C)
{
    const uint32_t* A = QKV ? g_xa   : reinterpret_cast<const uint32_t*>(g_ao);
    const uint32_t* W = QKV ? g_wqkv : g_wproj;
    const float* bias = QKV ? g_in_qkv_b : g_in_proj_b;

    constexpr int BM = 128, BN = 128, BK = 16, PITCH = 20;
    constexpr int ITERS = K / BK;
    __shared__ uint32_t As[2][BM * PITCH];
    __shared__ uint32_t Bs[2][BN * PITCH];

    const int tid  = threadIdx.x;
    const int warp = tid >> 5;
    const int lane = tid & 31;
    const int wm = (warp & 1) * 64;
    const int wn = (warp >> 1) * 64;
    const int qr = lane >> 2;
    const int qk = lane & 3;

    const int rowA = blockIdx.y * BM;
    const int colB = blockIdx.x * BN;
    const uint32_t* Ab = A + (size_t)rowA * K;
    const uint32_t* Wb = W + (size_t)colB * K;

    // Copy assignment: 512 16B-chunks per tile per matrix; 4 per thread.
    const int cm0 = tid >> 2;        // base row (0..31), +32*i
    const int ch  = (tid & 3) << 2;  // chunk k-offset 0,4,8,12

    auto issue_stage = [&](int s, int kt) {
        #pragma unroll
        for (int i = 0; i < 4; i++) {
            const int m = cm0 + i * 32;
            const uint32_t da = (uint32_t)__cvta_generic_to_shared(&As[s][m * PITCH + ch]);
            cp_async16(da, Ab + (size_t)m * K + kt + ch);
            const uint32_t db = (uint32_t)__cvta_generic_to_shared(&Bs[s][m * PITCH + ch]);
            cp_async16(db, Wb + (size_t)m * K + kt + ch);
        }
        asm volatile("cp.async.commit_group;");
    };

    float acc[4][8][4] = {};

    issue_stage(0, 0);
    for (int it = 0; it < ITERS; it++) {
        if (it + 1 < ITERS) {
            issue_stage((it + 1) & 1, (it + 1) * BK);
            asm volatile("cp.async.wait_group 1;");
        } else {
            asm volatile("cp.async.wait_group 0;");
        }
        __syncthreads();

        const uint32_t* as = As[it & 1];
        const uint32_t* bs = Bs[it & 1];
        #pragma unroll
        for (int ks = 0; ks < 2; ks++) {
            const int k0 = ks * 8;
            uint32_t af[4][4], bf[8][2];
            #pragma unroll
            for (int mt = 0; mt < 4; mt++) {
                const int m0 = wm + mt * 16;
                af[mt][0] = as[(m0 + qr    ) * PITCH + k0 + qk    ];
                af[mt][1] = as[(m0 + qr + 8) * PITCH + k0 + qk    ];
                af[mt][2] = as[(m0 + qr    ) * PITCH + k0 + qk + 4];
                af[mt][3] = as[(m0 + qr + 8) * PITCH + k0 + qk + 4];
            }
            #pragma unroll
            for (int nt = 0; nt < 8; nt++) {
                const int n0 = wn + nt * 8;
                bf[nt][0] = bs[(n0 + qr) * PITCH + k0 + qk    ];
                bf[nt][1] = bs[(n0 + qr) * PITCH + k0 + qk + 4];
            }
            #pragma unroll
            for (int mt = 0; mt < 4; mt++)
                #pragma unroll
                for (int nt = 0; nt < 8; nt++)
                    mma_tf32(acc[mt][nt], af[mt], bf[nt][0], bf[nt][1]);
        }
        __syncthreads();
    }

    #pragma unroll
    for (int mt = 0; mt < 4; mt++) {
        #pragma unroll
        for (int nt = 0; nt < 8; nt++) {
            #pragma unroll
            for (int rg = 0; rg < 4; rg++) {
                const int m = rowA + wm + mt * 16 + qr + ((rg >> 1) << 3);
                const int n = colB + wn + nt * 8 + (qk << 1) + (rg & 1);
                const float v = acc[mt][nt][rg] + bias[n];
                if (QKV) {
                    const int which = n >> 10;
                    float* dst = (which == 0) ? g_q : (which == 1) ? g_k : g_v;
                    const int b = m >> 11, s = m & (S_ - 1);
                    const int c = n & (E_ - 1);
                    const int h = c >> 6, d = c & (D_ - 1);
                    dst[(((size_t)(b * H_ + h)) * S_ + s) * D_ + d] = v;
                } else {
                    C[(size_t)m * N + n] = v;
                }
            }
        }
    }
}

// ---------------------------------------------------------------------------
// Tensor-core causal flash attention (UNCHANGED math; epilogue now emits
// tf32 bits into g_ao so the proj GEMM can consume it directly).
// ---------------------------------------------------------------------------
constexpr int KLD = 68;
constexpr int VLD = 72;

__global__ __launch_bounds__(128)
void flash_attn_mma_kernel()
{
    const int qi = blockIdx.x;
    const int bh = blockIdx.y;
    const float* Qg = g_q + (size_t)bh * S_ * D_;
    const float* Kg = g_k + (size_t)bh * S_ * D_;
    const float* Vg = g_v + (size_t)bh * S_ * D_;

    __shared__ uint32_t Ks[64 * KLD];
    __shared__ uint32_t Vs[64 * VLD];

    const int tid  = threadIdx.x;
    const int warp = tid >> 5;
    const int lane = tid & 31;
    const int qr = lane >> 2;
    const int qk = lane & 3;
    const int qrow0 = qi * 64 + warp * 16 + qr;

    uint32_t qa_hi[8][4], qa_lo[8][4];
    #pragma unroll
    for (int ks = 0; ks < 8; ks++) {
        const int c0 = ks * 8 + qk, c1 = c0 + 4;
        const float vals[4] = {
            Qg[(size_t)qrow0 * D_ + c0]       * 0.125f,
            Qg[(size_t)(qrow0 + 8) * D_ + c0] * 0.125f,
            Qg[(size_t)qrow0 * D_ + c1]       * 0.125f,
            Qg[(size_t)(qrow0 + 8) * D_ + c1] * 0.125f };
        #pragma unroll
        for (int t = 0; t < 4; t++) {
            const uint32_t hb = f2tf32(vals[t]);
            qa_hi[ks][t] = hb;
            qa_lo[ks][t] = f2tf32(vals[t] - __uint_as_float(hb));
        }
    }

    float o[8][4] = {};
    float m0 = -1e30f, m1 = -1e30f, l0 = 0.f, l1 = 0.f;

    const int frow = tid >> 1;
    const int fcol = (tid & 1) * 32;

    for (int jt = 0; jt <= qi; jt++) {
        const int kv0 = jt * 64;
        __syncthreads();
        #pragma unroll
        for (int t = 0; t < 8; t++) {
            const int c = fcol + t * 4;
            float4 kv4 = *reinterpret_cast<const float4*>(Kg + (size_t)(kv0 + frow) * D_ + c);
            float4 vv4 = *reinterpret_cast<const float4*>(Vg + (size_t)(kv0 + frow) * D_ + c);
            Ks[frow * KLD + c + 0] = f2tf32(kv4.x);
            Ks[frow * KLD + c + 1] = f2tf32(kv4.y);
            Ks[frow * KLD + c + 2] = f2tf32(kv4.z);
            Ks[frow * KLD + c + 3] = f2tf32(kv4.w);
            Vs[frow * VLD + c + 0] = f2tf32(vv4.x);
            Vs[frow * VLD + c + 1] = f2tf32(vv4.y);
            Vs[frow * VLD + c + 2] = f2tf32(vv4.z);
            Vs[frow * VLD + c + 3] = f2tf32(vv4.w);
        }
        __syncthreads();

        float sc[8][4] = {};
        #pragma unroll
        for (int ks = 0; ks < 8; ks++) {
            const int k0 = ks * 8;
            #pragma unroll
            for (int nt = 0; nt < 8; nt++) {
                const uint32_t b0 = Ks[(nt * 8 + qr) * KLD + k0 + qk];
                const uint32_t b1 = Ks[(nt * 8 + qr) * KLD + k0 + qk + 4];
                mma_tf32(sc[nt], qa_hi[ks], b0, b1);
                mma_tf32(sc[nt], qa_lo[ks], b0, b1);
            }
        }

        if (jt == qi) {
            #pragma unroll
            for (int nt = 0; nt < 8; nt++)
                #pragma unroll
                for (int rg = 0; rg < 4; rg++) {
                    const int kv = kv0 + nt * 8 + (qk << 1) + (rg & 1);
                    const int qrow = qrow0 + ((rg >> 1) << 3);
                    if (kv > qrow) sc[nt][rg] = -1e30f;
                }
        }

        {
            float mx = -1e30f;
            #pragma unroll
            for (int nt = 0; nt < 8; nt++) mx = fmaxf(mx, fmaxf(sc[nt][0], sc[nt][1]));
            mx = fmaxf(mx, __shfl_xor_sync(0xffffffffu, mx, 1));
            mx = fmaxf(mx, __shfl_xor_sync(0xffffffffu, mx, 2));
            const float mn = fmaxf(m0, mx);
            const float alpha = fexp(m0 - mn);
            m0 = mn;
            float sum = 0.f;
            #pragma unroll
            for (int nt = 0; nt < 8; nt++) {
                sc[nt][0] = fexp(sc[nt][0] - mn);
                sc[nt][1] = fexp(sc[nt][1] - mn);
                sum += sc[nt][0] + sc[nt][1];
            }
            sum += __shfl_xor_sync(0xffffffffu, sum, 1);
            sum += __shfl_xor_sync(0xffffffffu, sum, 2);
            l0 = l0 * alpha + sum;
            #pragma unroll
            for (int nt = 0; nt < 8; nt++) { o[nt][0] *= alpha; o[nt][1] *= alpha; }
        }
        {
            float mx = -1e30f;
            #pragma unroll
            for (int nt = 0; nt < 8; nt++) mx = fmaxf(mx, fmaxf(sc[nt][2], sc[nt][3]));
            mx = fmaxf(mx, __shfl_xor_sync(0xffffffffu, mx, 1));
            mx = fmaxf(mx, __shfl_xor_sync(0xffffffffu, mx, 2));
            const float mn = fmaxf(m1, mx);
            const float alpha = fexp(m1 - mn);
            m1 = mn;
            float sum = 0.f;
            #pragma unroll
            for (int nt = 0; nt < 8; nt++) {
                sc[nt][2] = fexp(sc[nt][2] - mn);
                sc[nt][3] = fexp(sc[nt][3] - mn);
                sum += sc[nt][2] + sc[nt][3];
            }
            sum += __shfl_xor_sync(0xffffffffu, sum, 1);
            sum += __shfl_xor_sync(0xffffffffu, sum, 2);
            l1 = l1 * alpha + sum;
            #pragma unroll
            for (int nt = 0; nt < 8; nt++) { o[nt][2] *= alpha; o[nt][3] *= alpha; }
        }

        #pragma unroll
        for (int ks = 0; ks < 8; ks++) {
            const int Ls  = (qr << 2) + (qk >> 1);
            const int Ls2 = Ls + 2;
            const bool oddp = (qk & 1);

            const float t00 = __shfl_sync(0xffffffffu, sc[ks][0], Ls);
            const float t01 = __shfl_sync(0xffffffffu, sc[ks][1], Ls);
            const float t20 = __shfl_sync(0xffffffffu, sc[ks][2], Ls);
            const float t21 = __shfl_sync(0xffffffffu, sc[ks][3], Ls);
            const float u00 = __shfl_sync(0xffffffffu, sc[ks][0], Ls2);
            const float u01 = __shfl_sync(0xffffffffu, sc[ks][1], Ls2);
            const float u20 = __shfl_sync(0xffffffffu, sc[ks][2], Ls2);
            const float u21 = __shfl_sync(0xffffffffu, sc[ks][3], Ls2);

            uint32_t pa[4];
            pa[0] = f2tf32(oddp ? t01 : t00);
            pa[1] = f2tf32(oddp ? t21 : t20);
            pa[2] = f2tf32(oddp ? u01 : u00);
            pa[3] = f2tf32(oddp ? u21 : u20);

            const int k0 = ks * 8;
            #pragma unroll
            for (int nt = 0; nt < 8; nt++) {
                const uint32_t b0 = Vs[(k0 + qk) * VLD + nt * 8 + qr];
                const uint32_t b1 = Vs[(k0 + qk + 4) * VLD + nt * 8 + qr];
                mma_tf32(o[nt], pa, b0, b1);
            }
        }
    }

    // Finalize: divide by l, emit TF32 BITS (proj GEMM consumes g_ao directly)
    const int b = bh >> 4, h = bh & 15;
    const float inv0 = 1.f / l0, inv1 = 1.f / l1;
    #pragma unroll
    for (int nt = 0; nt < 8; nt++) {
        const int d0 = nt * 8 + (qk << 1);
        uint2 r0, r1;
        r0.x = f2tf32(o[nt][0] * inv0); r0.y = f2tf32(o[nt][1] * inv0);
        r1.x = f2tf32(o[nt][2] * inv1); r1.y = f2tf32(o[nt][3] * inv1);
        *reinterpret_cast<uint2*>(g_ao + ((size_t)(b * S_ + qrow0)) * E_ + h * 64 + d0) = r0;
        *reinterpret_cast<uint2*>(g_ao + ((size_t)(b * S_ + qrow0 + 8)) * E_ + h * 64 + d0) = r1;
    }
}

}  // namespace

extern "C" void kernel_launch(void* const* d_in, const int* in_sizes, int n_in,
                              void* d_out, int out_size)
{
    (void)out_size;
    InArgs a;
    a.n = (n_in < 8) ? n_in : 8;
    for (int i = 0; i < 8; i++) {
        a.p[i]  = (i < a.n) ? (const float*)d_in[i] : nullptr;
        a.sz[i] = (i < a.n) ? (long long)in_sizes[i] : 0;
    }

    classify_kernel<<<1, 256>>>(a);

    // Pre-convert operands to tf32 bits
    convert_tf32_kernel<0, MROWS * E_>   <<<512, 256>>>();
    convert_tf32_kernel<1, 3 * E_ * E_>  <<<512, 256>>>();
    convert_tf32_kernel<2, E_ * E_>      <<<256, 256>>>();

    // 1) QKV GEMM
    {
        dim3 grid(3 * E_ / 128, MROWS / 128);
        tf32_gemm_kernel<3 * E_, E_, true><<<grid, 128>>>(nullptr);
    }
    // 2) Causal flash attention
    {
        dim3 grid(S_ / 64, B_ * H_);
        flash_attn_mma_kernel<<<grid, 128>>>();
    }
    // 3) Output projection
    {
        dim3 grid(E_ / 128, MROWS / 128);
        tf32_gemm_kernel<E_, E_, false><<<grid, 128>>>((float*)d_out);
    }
}

// round 10
// speedup vs baseline: 2.6392x; 1.0743x over previous
#include <cuda_runtime.h>
#include <math.h>
#include <stdint.h>

namespace {

constexpr int B_ = 2;
constexpr int S_ = 2048;
constexpr int H_ = 16;
constexpr int D_ = 64;
constexpr int E_ = 1024;
constexpr int MROWS = B_ * S_;   // 4096

// Scratch (device globals: allocation-free per harness rules)
__device__ float    g_q[(size_t)B_ * H_ * S_ * D_];   // [b,h,s,d] fp32 (needs hi/lo split)
__device__ uint32_t g_kt[(size_t)B_ * H_ * S_ * D_];  // [b,h,s,d] tf32 bits
__device__ uint32_t g_vt[(size_t)B_ * H_ * S_ * D_];  // [b,h,s,d] tf32 bits
__device__ float    g_ao[(size_t)MROWS * E_];          // [b,s,e] holds TF32 BITS

// Pre-converted tf32 operands
__device__ uint32_t g_xa[(size_t)MROWS * E_];        // x as tf32
__device__ uint32_t g_wqkv[(size_t)3 * E_ * E_];     // qkv_w as tf32
__device__ uint32_t g_wproj[(size_t)E_ * E_];        // proj_w as tf32

// Input pointers resolved ON DEVICE by the classifier kernel.
__device__ const float* g_in_x;
__device__ const float* g_in_qkv_w;
__device__ const float* g_in_qkv_b;
__device__ const float* g_in_proj_w;
__device__ const float* g_in_proj_b;

struct InArgs {
    const float* p[8];
    long long    sz[8];
    int          n;
};

// ---------------------------------------------------------------------------
// Classifier (UNCHANGED): identify inputs by size rank + data statistics.
// ---------------------------------------------------------------------------
__global__ __launch_bounds__(256)
void classify_kernel(InArgs a)
{
    __shared__ float red[256];
    __shared__ float msq[8];
    const int tid = threadIdx.x;

    for (int c = 0; c < a.n; c++) {
        float s = 0.f;
        #pragma unroll
        for (int i = tid; i < 2048; i += 256) {
            const float v = a.p[c][i];
            s += v * v;
        }
        red[tid] = s;
        __syncthreads();
        for (int st = 128; st; st >>= 1) {
            if (tid < st) red[tid] += red[tid + st];
            __syncthreads();
        }
        if (tid == 0) msq[c] = red[0] * (1.f / 2048.f);
        __syncthreads();
    }

    if (tid == 0) {
        int ord[8];
        for (int i = 0; i < a.n; i++) ord[i] = i;
        for (int i = 1; i < a.n; i++) {
            const int o = ord[i];
            const long long s = a.sz[o];
            int j = i - 1;
            while (j >= 0 && a.sz[ord[j]] > s) { ord[j + 1] = ord[j]; j--; }
            ord[j + 1] = o;
        }
        g_in_proj_b = a.p[ord[0]];
        g_in_qkv_b  = a.p[ord[1]];

        int xi = -1;
        for (int r = 2; r < a.n; r++) {
            const float m = msq[ord[r]];
            if (m > 0.3f && m < 3.f) { xi = ord[r]; break; }
        }
        int w0 = -1, w1 = -1;
        for (int r = 2; r < a.n; r++) {
            if (ord[r] == xi) continue;
            if (w0 < 0) { w0 = ord[r]; continue; }
            if (w1 < 0) { w1 = ord[r]; break; }
        }
        g_in_proj_w = a.p[w0];
        g_in_qkv_w  = a.p[w1];
        if (xi < 0) xi = (a.n >= 5) ? ord[4] : ord[a.n - 1];
        g_in_x = a.p[xi];
    }
}

__device__ __forceinline__ uint32_t f2tf32(float f) {
    uint32_t u;
    asm("cvt.rna.tf32.f32 %0, %1;" : "=r"(u) : "f"(f));
    return u;
}

// Pre-convert an operand tensor to tf32 bits. WHICH: 0=x, 1=qkv_w, 2=proj_w.
template <int WHICH, int NELEM>
__global__ __launch_bounds__(256)
void convert_tf32_kernel()
{
    const float* src = (WHICH == 0) ? g_in_x : (WHICH == 1) ? g_in_qkv_w : g_in_proj_w;
    uint32_t*    dst = (WHICH == 0) ? g_xa   : (WHICH == 1) ? g_wqkv    : g_wproj;
    const int stride = gridDim.x * 256;
    for (int i = blockIdx.x * 256 + threadIdx.x; i < NELEM / 4; i += stride) {
        const float4 v = reinterpret_cast<const float4*>(src)[i];
        uint4 o;
        o.x = f2tf32(v.x); o.y = f2tf32(v.y);
        o.z = f2tf32(v.z); o.w = f2tf32(v.w);
        reinterpret_cast<uint4*>(dst)[i] = o;
    }
}

// Fast exp on FMA/ALU pipes (no MUFU). Valid for x <= 0 (clamped at -87).
__device__ __forceinline__ float fexp(float x) {
    x = fmaxf(x, -87.0f);
    const float t = x * 1.4426950408889634f;
    const int   ei = __float2int_rd(t);
    const float f  = t - (float)ei;
    float p = 1.535336188319500e-4f;
    p = fmaf(p, f, 1.339887440266574e-3f);
    p = fmaf(p, f, 9.618437357674640e-3f);
    p = fmaf(p, f, 5.550332471162809e-2f);
    p = fmaf(p, f, 2.402264791363012e-1f);
    p = fmaf(p, f, 6.931472028550421e-1f);
    p = fmaf(p, f, 1.0f);
    return __uint_as_float(__float_as_uint(p) + ((uint32_t)ei << 23));
}

__device__ __forceinline__ void mma_tf32(float c[4], const uint32_t a[4],
                                         uint32_t b0, uint32_t b1) {
    asm volatile(
        "mma.sync.aligned.m16n8k8.row.col.f32.tf32.tf32.f32 "
        "{%0,%1,%2,%3}, {%4,%5,%6,%7}, {%8,%9}, {%0,%1,%2,%3};"
        : "+f"(c[0]), "+f"(c[1]), "+f"(c[2]), "+f"(c[3])
        : "r"(a[0]), "r"(a[1]), "r"(a[2]), "r"(a[3]), "r"(b0), "r"(b1));
}

__device__ __forceinline__ void cp_async16(uint32_t smem_dst, const void* gsrc) {
    asm volatile("cp.async.cg.shared.global [%0], [%1], 16;"
                 :: "r"(smem_dst), "l"(gsrc));
}

// ---------------------------------------------------------------------------
// tf32 tensor-core GEMM, cp.async double-buffered (UNCHANGED structure).
// QKV epilogue now stores K and V as TF32 BITS (bit-identical to converting
// inside attention); Q stays fp32 for the hi/lo split.
// ---------------------------------------------------------------------------
template <int N, int K, bool QKV>
__global__ __launch_bounds__(128, 2)
void tf32_gemm_kernel(float* __restrict__ C)
{
    const uint32_t* A = QKV ? g_xa   : reinterpret_cast<const uint32_t*>(g_ao);
    const uint32_t* W = QKV ? g_wqkv : g_wproj;
    const float* bias = QKV ? g_in_qkv_b : g_in_proj_b;

    constexpr int BM = 128, BN = 128, BK = 16, PITCH = 20;
    constexpr int ITERS = K / BK;
    __shared__ __align__(16) uint32_t As[2][BM * PITCH];
    __shared__ __align__(16) uint32_t Bs[2][BN * PITCH];

    const int tid  = threadIdx.x;
    const int warp = tid >> 5;
    const int lane = tid & 31;
    const int wm = (warp & 1) * 64;
    const int wn = (warp >> 1) * 64;
    const int qr = lane >> 2;
    const int qk = lane & 3;

    const int rowA = blockIdx.y * BM;
    const int colB = blockIdx.x * BN;
    const uint32_t* Ab = A + (size_t)rowA * K;
    const uint32_t* Wb = W + (size_t)colB * K;

    const int cm0 = tid >> 2;
    const int ch  = (tid & 3) << 2;

    auto issue_stage = [&](int s, int kt) {
        #pragma unroll
        for (int i = 0; i < 4; i++) {
            const int m = cm0 + i * 32;
            const uint32_t da = (uint32_t)__cvta_generic_to_shared(&As[s][m * PITCH + ch]);
            cp_async16(da, Ab + (size_t)m * K + kt + ch);
            const uint32_t db = (uint32_t)__cvta_generic_to_shared(&Bs[s][m * PITCH + ch]);
            cp_async16(db, Wb + (size_t)m * K + kt + ch);
        }
        asm volatile("cp.async.commit_group;");
    };

    float acc[4][8][4] = {};

    issue_stage(0, 0);
    for (int it = 0; it < ITERS; it++) {
        if (it + 1 < ITERS) {
            issue_stage((it + 1) & 1, (it + 1) * BK);
            asm volatile("cp.async.wait_group 1;");
        } else {
            asm volatile("cp.async.wait_group 0;");
        }
        __syncthreads();

        const uint32_t* as = As[it & 1];
        const uint32_t* bs = Bs[it & 1];
        #pragma unroll
        for (int ks = 0; ks < 2; ks++) {
            const int k0 = ks * 8;
            uint32_t af[4][4], bf[8][2];
            #pragma unroll
            for (int mt = 0; mt < 4; mt++) {
                const int m0 = wm + mt * 16;
                af[mt][0] = as[(m0 + qr    ) * PITCH + k0 + qk    ];
                af[mt][1] = as[(m0 + qr + 8) * PITCH + k0 + qk    ];
                af[mt][2] = as[(m0 + qr    ) * PITCH + k0 + qk + 4];
                af[mt][3] = as[(m0 + qr + 8) * PITCH + k0 + qk + 4];
            }
            #pragma unroll
            for (int nt = 0; nt < 8; nt++) {
                const int n0 = wn + nt * 8;
                bf[nt][0] = bs[(n0 + qr) * PITCH + k0 + qk    ];
                bf[nt][1] = bs[(n0 + qr) * PITCH + k0 + qk + 4];
            }
            #pragma unroll
            for (int mt = 0; mt < 4; mt++)
                #pragma unroll
                for (int nt = 0; nt < 8; nt++)
                    mma_tf32(acc[mt][nt], af[mt], bf[nt][0], bf[nt][1]);
        }
        __syncthreads();
    }

    #pragma unroll
    for (int mt = 0; mt < 4; mt++) {
        #pragma unroll
        for (int nt = 0; nt < 8; nt++) {
            #pragma unroll
            for (int rg = 0; rg < 4; rg++) {
                const int m = rowA + wm + mt * 16 + qr + ((rg >> 1) << 3);
                const int n = colB + wn + nt * 8 + (qk << 1) + (rg & 1);
                const float v = acc[mt][nt][rg] + bias[n];
                if (QKV) {
                    const int which = n >> 10;
                    const int b = m >> 11, s = m & (S_ - 1);
                    const int c = n & (E_ - 1);
                    const int h = c >> 6, d = c & (D_ - 1);
                    const size_t off = (((size_t)(b * H_ + h)) * S_ + s) * D_ + d;
                    if (which == 0)      g_q[off]  = v;
                    else if (which == 1) g_kt[off] = f2tf32(v);
                    else                 g_vt[off] = f2tf32(v);
                } else {
                    C[(size_t)m * N + n] = v;
                }
            }
        }
    }
}

// ---------------------------------------------------------------------------
// Tensor-core causal flash attention. K/V are pre-converted tf32 in GMEM ->
// cp.async double-buffered tile loads (prefetch jt+1 during compute of jt).
// Descending-qi schedule: longest CTAs first.
// ---------------------------------------------------------------------------
constexpr int KLD = 68;
constexpr int VLD = 72;

__global__ __launch_bounds__(128)
void flash_attn_mma_kernel()
{
    const int qi = (int)(gridDim.x - 1) - (int)blockIdx.x;   // descending work
    const int bh = blockIdx.y;
    const float*    Qg = g_q  + (size_t)bh * S_ * D_;
    const uint32_t* Kg = g_kt + (size_t)bh * S_ * D_;
    const uint32_t* Vg = g_vt + (size_t)bh * S_ * D_;

    __shared__ __align__(16) uint32_t Ks[2][64 * KLD];
    __shared__ __align__(16) uint32_t Vs[2][64 * VLD];

    const int tid  = threadIdx.x;
    const int warp = tid >> 5;
    const int lane = tid & 31;
    const int qr = lane >> 2;
    const int qk = lane & 3;
    const int qrow0 = qi * 64 + warp * 16 + qr;

    // K/V tile copy assignment: row frow, 8 16B-chunks starting at fcol
    const int frow = tid >> 1;
    const int fcol = (tid & 1) * 32;

    auto issue_kv = [&](int s, int jt) {
        const size_t gbase = (size_t)(jt * 64 + frow) * D_ + fcol;
        #pragma unroll
        for (int t = 0; t < 8; t++) {
            const int c = fcol + t * 4;
            cp_async16((uint32_t)__cvta_generic_to_shared(&Ks[s][frow * KLD + c]),
                       Kg + gbase + t * 4);
            cp_async16((uint32_t)__cvta_generic_to_shared(&Vs[s][frow * VLD + c]),
                       Vg + gbase + t * 4);
        }
        asm volatile("cp.async.commit_group;");
    };

    // Preload Q a-frags (scaled, split hi/lo), loop-invariant.
    uint32_t qa_hi[8][4], qa_lo[8][4];
    #pragma unroll
    for (int ks = 0; ks < 8; ks++) {
        const int c0 = ks * 8 + qk, c1 = c0 + 4;
        const float vals[4] = {
            Qg[(size_t)qrow0 * D_ + c0]       * 0.125f,
            Qg[(size_t)(qrow0 + 8) * D_ + c0] * 0.125f,
            Qg[(size_t)qrow0 * D_ + c1]       * 0.125f,
            Qg[(size_t)(qrow0 + 8) * D_ + c1] * 0.125f };
        #pragma unroll
        for (int t = 0; t < 4; t++) {
            const uint32_t hb = f2tf32(vals[t]);
            qa_hi[ks][t] = hb;
            qa_lo[ks][t] = f2tf32(vals[t] - __uint_as_float(hb));
        }
    }

    float o[8][4] = {};
    float m0 = -1e30f, m1 = -1e30f, l0 = 0.f, l1 = 0.f;

    issue_kv(0, 0);
    for (int jt = 0; jt <= qi; jt++) {
        const int kv0 = jt * 64;
        if (jt < qi) {
            issue_kv((jt + 1) & 1, jt + 1);
            asm volatile("cp.async.wait_group 1;");
        } else {
            asm volatile("cp.async.wait_group 0;");
        }
        __syncthreads();

        const uint32_t* ks_ = Ks[jt & 1];
        const uint32_t* vs_ = Vs[jt & 1];

        float sc[8][4] = {};
        #pragma unroll
        for (int ks = 0; ks < 8; ks++) {
            const int k0 = ks * 8;
            #pragma unroll
            for (int nt = 0; nt < 8; nt++) {
                const uint32_t b0 = ks_[(nt * 8 + qr) * KLD + k0 + qk];
                const uint32_t b1 = ks_[(nt * 8 + qr) * KLD + k0 + qk + 4];
                mma_tf32(sc[nt], qa_hi[ks], b0, b1);
                mma_tf32(sc[nt], qa_lo[ks], b0, b1);
            }
        }

        if (jt == qi) {
            #pragma unroll
            for (int nt = 0; nt < 8; nt++)
                #pragma unroll
                for (int rg = 0; rg < 4; rg++) {
                    const int kv = kv0 + nt * 8 + (qk << 1) + (rg & 1);
                    const int qrow = qrow0 + ((rg >> 1) << 3);
                    if (kv > qrow) sc[nt][rg] = -1e30f;
                }
        }

        {
            float mx = -1e30f;
            #pragma unroll
            for (int nt = 0; nt < 8; nt++) mx = fmaxf(mx, fmaxf(sc[nt][0], sc[nt][1]));
            mx = fmaxf(mx, __shfl_xor_sync(0xffffffffu, mx, 1));
            mx = fmaxf(mx, __shfl_xor_sync(0xffffffffu, mx, 2));
            const float mn = fmaxf(m0, mx);
            const float alpha = fexp(m0 - mn);
            m0 = mn;
            float sum = 0.f;
            #pragma unroll
            for (int nt = 0; nt < 8; nt++) {
                sc[nt][0] = fexp(sc[nt][0] - mn);
                sc[nt][1] = fexp(sc[nt][1] - mn);
                sum += sc[nt][0] + sc[nt][1];
            }
            sum += __shfl_xor_sync(0xffffffffu, sum, 1);
            sum += __shfl_xor_sync(0xffffffffu, sum, 2);
            l0 = l0 * alpha + sum;
            #pragma unroll
            for (int nt = 0; nt < 8; nt++) { o[nt][0] *= alpha; o[nt][1] *= alpha; }
        }
        {
            float mx = -1e30f;
            #pragma unroll
            for (int nt = 0; nt < 8; nt++) mx = fmaxf(mx, fmaxf(sc[nt][2], sc[nt][3]));
            mx = fmaxf(mx, __shfl_xor_sync(0xffffffffu, mx, 1));
            mx = fmaxf(mx, __shfl_xor_sync(0xffffffffu, mx, 2));
            const float mn = fmaxf(m1, mx);
            const float alpha = fexp(m1 - mn);
            m1 = mn;
            float sum = 0.f;
            #pragma unroll
            for (int nt = 0; nt < 8; nt++) {
                sc[nt][2] = fexp(sc[nt][2] - mn);
                sc[nt][3] = fexp(sc[nt][3] - mn);
                sum += sc[nt][2] + sc[nt][3];
            }
            sum += __shfl_xor_sync(0xffffffffu, sum, 1);
            sum += __shfl_xor_sync(0xffffffffu, sum, 2);
            l1 = l1 * alpha + sum;
            #pragma unroll
            for (int nt = 0; nt < 8; nt++) { o[nt][2] *= alpha; o[nt][3] *= alpha; }
        }

        #pragma unroll
        for (int ks = 0; ks < 8; ks++) {
            const int Ls  = (qr << 2) + (qk >> 1);
            const int Ls2 = Ls + 2;
            const bool oddp = (qk & 1);

            const float t00 = __shfl_sync(0xffffffffu, sc[ks][0], Ls);
            const float t01 = __shfl_sync(0xffffffffu, sc[ks][1], Ls);
            const float t20 = __shfl_sync(0xffffffffu, sc[ks][2], Ls);
            const float t21 = __shfl_sync(0xffffffffu, sc[ks][3], Ls);
            const float u00 = __shfl_sync(0xffffffffu, sc[ks][0], Ls2);
            const float u01 = __shfl_sync(0xffffffffu, sc[ks][1], Ls2);
            const float u20 = __shfl_sync(0xffffffffu, sc[ks][2], Ls2);
            const float u21 = __shfl_sync(0xffffffffu, sc[ks][3], Ls2);

            uint32_t pa[4];
            pa[0] = f2tf32(oddp ? t01 : t00);
            pa[1] = f2tf32(oddp ? t21 : t20);
            pa[2] = f2tf32(oddp ? u01 : u00);
            pa[3] = f2tf32(oddp ? u21 : u20);

            const int k0 = ks * 8;
            #pragma unroll
            for (int nt = 0; nt < 8; nt++) {
                const uint32_t b0 = vs_[(k0 + qk) * VLD + nt * 8 + qr];
                const uint32_t b1 = vs_[(k0 + qk + 4) * VLD + nt * 8 + qr];
                mma_tf32(o[nt], pa, b0, b1);
            }
        }
        __syncthreads();   // all reads of this stage done before next issue
    }

    // Finalize: divide by l, emit TF32 BITS (proj GEMM consumes g_ao directly)
    const int b = bh >> 4, h = bh & 15;
    const float inv0 = 1.f / l0, inv1 = 1.f / l1;
    #pragma unroll
    for (int nt = 0; nt < 8; nt++) {
        const int d0 = nt * 8 + (qk << 1);
        uint2 r0, r1;
        r0.x = f2tf32(o[nt][0] * inv0); r0.y = f2tf32(o[nt][1] * inv0);
        r1.x = f2tf32(o[nt][2] * inv1); r1.y = f2tf32(o[nt][3] * inv1);
        *reinterpret_cast<uint2*>(g_ao + ((size_t)(b * S_ + qrow0)) * E_ + h * 64 + d0) = r0;
        *reinterpret_cast<uint2*>(g_ao + ((size_t)(b * S_ + qrow0 + 8)) * E_ + h * 64 + d0) = r1;
    }
}

}  // namespace

extern "C" void kernel_launch(void* const* d_in, const int* in_sizes, int n_in,
                              void* d_out, int out_size)
{
    (void)out_size;
    InArgs a;
    a.n = (n_in < 8) ? n_in : 8;
    for (int i = 0; i < 8; i++) {
        a.p[i]  = (i < a.n) ? (const float*)d_in[i] : nullptr;
        a.sz[i] = (i < a.n) ? (long long)in_sizes[i] : 0;
    }

    classify_kernel<<<1, 256>>>(a);

    // Pre-convert operands to tf32 bits
    convert_tf32_kernel<0, MROWS * E_>   <<<512, 256>>>();
    convert_tf32_kernel<1, 3 * E_ * E_>  <<<512, 256>>>();
    convert_tf32_kernel<2, E_ * E_>      <<<256, 256>>>();

    // 1) QKV GEMM (K/V emitted as tf32 bits)
    {
        dim3 grid(3 * E_ / 128, MROWS / 128);
        tf32_gemm_kernel<3 * E_, E_, true><<<grid, 128>>>(nullptr);
    }
    // 2) Causal flash attention (cp.async double-buffered K/V)
    {
        dim3 grid(S_ / 64, B_ * H_);
        flash_attn_mma_kernel<<<grid, 128>>>();
    }
    // 3) Output projection
    {
        dim3 grid(E_ / 128, MROWS / 128);
        tf32_gemm_kernel<E_, E_, false><<<grid, 128>>>((float*)d_out);
    }
}